// round 2
// baseline (speedup 1.0000x reference)
#include <cuda_runtime.h>
#include <cstdint>

// ---------------- problem constants ----------------
#define NB   2
#define NC   256
#define HH   64
#define NPIX 4096           // 64*64
#define NN   4096           // attention sequence length
#define QKD  32
#define NCLS 19

// ---------------- scratch (device globals; no allocation allowed) ----------
__device__ float g_modal [NB*NCLS*NPIX];
__device__ float g_amodal[NB*NCLS*NPIX];
__device__ float g_q     [NB*QKD*NPIX];
__device__ float g_kk    [NB*QKD*NPIX];
__device__ float g_v     [(size_t)NB*NC*NPIX];
__device__ float g_comp  [(size_t)NB*NC*NPIX];
__device__ float g_outA  [(size_t)NB*NC*NPIX];
__device__ float g_outB  [(size_t)NB*NC*NPIX];
__device__ float g_outC  [(size_t)NB*NC*NPIX];
__device__ float g_P1    [(size_t)NB*NN*NN];
__device__ float g_P2    [(size_t)NB*NN*NN];
__device__ float g_rmax  [NB*NN];
__device__ float g_rinv  [NB*NN];
__device__ float g_cmax  [NB*NN];
__device__ float g_cinv  [NB*NN];
__device__ float g_y0    [NB*NC];
__device__ float g_se    [NB*NC];

// ======================================================================
// Generic 3x3 SAME conv, NCHW, input = concat of up to 3 channel segments.
// Block: 256 threads, 32x32 spatial tile, 8 output channels, 4 px/thread.
// Optional per-(oc,pixel) mask multiply (for modal/amodal branches).
// ======================================================================
__global__ __launch_bounds__(256) void conv3x3_k(
    const float* __restrict__ p0, int c0, int bs0,
    const float* __restrict__ p1, int c1, int bs1,
    const float* __restrict__ p2, int c2, int bs2,
    const float* __restrict__ wt,    // [Cout][Cin][3][3]
    const float* __restrict__ bias,  // [Cout]
    float* __restrict__ out, int outBS, int Cout,
    const float* __restrict__ mask, int maskBS)
{
    const int Cin = c0 + c1 + c2;
    const int tileIdx = blockIdx.x;            // 0..3
    const int ty0 = (tileIdx >> 1) * 32;
    const int tx0 = (tileIdx &  1) * 32;
    const int ocg = blockIdx.y * 8;
    const int b   = blockIdx.z;

    const int tid = threadIdx.x;
    const int tx  = tid & 31;
    const int ty  = tid >> 5;                  // 0..7

    __shared__ float in_s[34*34];
    __shared__ float ws[72];

    float acc[4][8];
    #pragma unroll
    for (int p = 0; p < 4; p++)
        #pragma unroll
        for (int o = 0; o < 8; o++) acc[p][o] = 0.f;

    for (int ic = 0; ic < Cin; ic++) {
        const float* src;
        if (ic < c0)           src = p0 + (size_t)b*bs0 + (size_t)ic       *NPIX;
        else if (ic < c0+c1)   src = p1 + (size_t)b*bs1 + (size_t)(ic-c0)   *NPIX;
        else                   src = p2 + (size_t)b*bs2 + (size_t)(ic-c0-c1)*NPIX;

        for (int i = tid; i < 34*34; i += 256) {
            int r = i / 34, c = i - r*34;
            int yy = ty0 + r - 1, xx = tx0 + c - 1;
            float v = 0.f;
            if (yy >= 0 && yy < HH && xx >= 0 && xx < HH) v = src[yy*HH + xx];
            in_s[i] = v;
        }
        if (tid < 72) {
            int o = tid / 9, t = tid - o*9;
            float wv = 0.f;
            if (ocg + o < Cout) wv = wt[((size_t)(ocg+o)*Cin + ic)*9 + t];
            ws[tid] = wv;
        }
        __syncthreads();

        float win[4][9];
        #pragma unroll
        for (int p = 0; p < 4; p++) {
            int py = ty + p*8;
            #pragma unroll
            for (int dy = 0; dy < 3; dy++)
                #pragma unroll
                for (int dx = 0; dx < 3; dx++)
                    win[p][dy*3+dx] = in_s[(py+dy)*34 + tx+dx];
        }
        #pragma unroll
        for (int o = 0; o < 8; o++) {
            #pragma unroll
            for (int t = 0; t < 9; t++) {
                float wv = ws[o*9 + t];
                #pragma unroll
                for (int p = 0; p < 4; p++) acc[p][o] += wv * win[p][t];
            }
        }
        __syncthreads();
    }

    #pragma unroll
    for (int o = 0; o < 8; o++) {
        int oc = ocg + o;
        if (oc >= Cout) break;
        float bv = bias ? bias[oc] : 0.f;
        #pragma unroll
        for (int p = 0; p < 4; p++) {
            int py = ty0 + ty + p*8;
            int px = tx0 + tx;
            size_t pix = (size_t)py*HH + px;
            float v = acc[p][o] + bv;
            if (mask) v *= mask[(size_t)b*maskBS + (size_t)oc*NPIX + pix];
            out[(size_t)b*outBS + (size_t)oc*NPIX + pix] = v;
        }
    }
}

// ======================================================================
// Flash-style softmax stats over rows of E = Q^T K  (Q,K: [B][32][N]).
// Call with (q,k) for row stats of E, (k,q) for column stats of E.
// One block = 64 rows; streams K in 64-col chunks; online max/sum.
// ======================================================================
__global__ __launch_bounds__(256) void attn_stats_k(
    const float* __restrict__ Q, const float* __restrict__ K,
    float* __restrict__ omax, float* __restrict__ oinv)
{
    const int b  = blockIdx.y;
    const int n0 = blockIdx.x * 64;
    const int tid = threadIdx.x;
    const int tx = tid & 15, ty = tid >> 4;

    __shared__ float qs[32][64];
    __shared__ float ks[32][64];
    __shared__ float redM[64][17];
    __shared__ float redS[64][17];

    const float* qb = Q + (size_t)b*QKD*NN;
    const float* kb = K + (size_t)b*QKD*NN;

    for (int i = tid; i < 32*16; i += 256) {
        int d = i >> 4, c4 = i & 15;
        *(float4*)&qs[d][c4*4] = *(const float4*)(qb + (size_t)d*NN + n0 + c4*4);
    }

    float M[4], S[4];
    #pragma unroll
    for (int i = 0; i < 4; i++) { M[i] = -1e30f; S[i] = 0.f; }

    for (int m0 = 0; m0 < NN; m0 += 64) {
        __syncthreads();
        for (int i = tid; i < 32*16; i += 256) {
            int d = i >> 4, c4 = i & 15;
            *(float4*)&ks[d][c4*4] = *(const float4*)(kb + (size_t)d*NN + m0 + c4*4);
        }
        __syncthreads();

        float e[4][4];
        #pragma unroll
        for (int i = 0; i < 4; i++)
            #pragma unroll
            for (int j = 0; j < 4; j++) e[i][j] = 0.f;

        #pragma unroll
        for (int d = 0; d < 32; d++) {
            float4 a  = *(const float4*)&qs[d][ty*4];
            float4 bv = *(const float4*)&ks[d][tx*4];
            float aa[4] = {a.x, a.y, a.z, a.w};
            float bb[4] = {bv.x, bv.y, bv.z, bv.w};
            #pragma unroll
            for (int i = 0; i < 4; i++)
                #pragma unroll
                for (int j = 0; j < 4; j++) e[i][j] += aa[i]*bb[j];
        }
        #pragma unroll
        for (int i = 0; i < 4; i++) {
            float lm = fmaxf(fmaxf(e[i][0], e[i][1]), fmaxf(e[i][2], e[i][3]));
            float nm = fmaxf(M[i], lm);
            float s = S[i] * __expf(M[i] - nm);
            #pragma unroll
            for (int j = 0; j < 4; j++) s += __expf(e[i][j] - nm);
            M[i] = nm; S[i] = s;
        }
    }
    __syncthreads();
    #pragma unroll
    for (int i = 0; i < 4; i++) { redM[ty*4+i][tx] = M[i]; redS[ty*4+i][tx] = S[i]; }
    __syncthreads();
    if (tid < 64) {
        float m = redM[tid][0], s = redS[tid][0];
        for (int j = 1; j < 16; j++) {
            float m2 = redM[tid][j], s2 = redS[tid][j];
            float nm = fmaxf(m, m2);
            s = s*__expf(m - nm) + s2*__expf(m2 - nm);
            m = nm;
        }
        omax[(size_t)b*NN + n0 + tid] = m;
        oinv[(size_t)b*NN + n0 + tid] = 1.f / s;
    }
}

// ======================================================================
// P kernel: compute E tile once, write both normalized softmax matrices:
//   P1[n][m] = exp(E[n,m]-rmax[n]) * rinv[n]   (row softmax)
//   P2[n][m] = exp(E[n,m]-cmax[m]) * cinv[m]   (col softmax)
// ======================================================================
__global__ __launch_bounds__(256) void attn_p_k(
    const float* __restrict__ Q, const float* __restrict__ K,
    const float* __restrict__ rmax, const float* __restrict__ rinv,
    const float* __restrict__ cmax, const float* __restrict__ cinv,
    float* __restrict__ P1, float* __restrict__ P2)
{
    const int b  = blockIdx.z;
    const int n0 = blockIdx.y * 64;
    const int m0 = blockIdx.x * 64;
    const int tid = threadIdx.x;
    const int tx = tid & 15, ty = tid >> 4;

    __shared__ float qs[32][64];
    __shared__ float ks[32][64];

    const float* qb = Q + (size_t)b*QKD*NN;
    const float* kb = K + (size_t)b*QKD*NN;

    for (int i = tid; i < 32*16; i += 256) {
        int d = i >> 4, c4 = i & 15;
        *(float4*)&qs[d][c4*4] = *(const float4*)(qb + (size_t)d*NN + n0 + c4*4);
        *(float4*)&ks[d][c4*4] = *(const float4*)(kb + (size_t)d*NN + m0 + c4*4);
    }
    __syncthreads();

    float e[4][4];
    #pragma unroll
    for (int i = 0; i < 4; i++)
        #pragma unroll
        for (int j = 0; j < 4; j++) e[i][j] = 0.f;

    #pragma unroll
    for (int d = 0; d < 32; d++) {
        float4 a  = *(const float4*)&qs[d][ty*4];
        float4 bv = *(const float4*)&ks[d][tx*4];
        float aa[4] = {a.x, a.y, a.z, a.w};
        float bb[4] = {bv.x, bv.y, bv.z, bv.w};
        #pragma unroll
        for (int i = 0; i < 4; i++)
            #pragma unroll
            for (int j = 0; j < 4; j++) e[i][j] += aa[i]*bb[j];
    }

    float rm[4], ri[4], cm[4], ci[4];
    #pragma unroll
    for (int i = 0; i < 4; i++) {
        rm[i] = rmax[(size_t)b*NN + n0 + ty*4 + i];
        ri[i] = rinv[(size_t)b*NN + n0 + ty*4 + i];
        cm[i] = cmax[(size_t)b*NN + m0 + tx*4 + i];
        ci[i] = cinv[(size_t)b*NN + m0 + tx*4 + i];
    }

    #pragma unroll
    for (int i = 0; i < 4; i++) {
        int n = n0 + ty*4 + i;
        float4 v1, v2;
        float* pv1 = (float*)&v1;
        float* pv2 = (float*)&v2;
        #pragma unroll
        for (int j = 0; j < 4; j++) {
            pv1[j] = __expf(e[i][j] - rm[i]) * ri[i];
            pv2[j] = __expf(e[i][j] - cm[j]) * ci[j];
        }
        size_t base = (size_t)b*NN*NN + (size_t)n*NN + m0 + tx*4;
        *(float4*)(P1 + base) = v1;
        *(float4*)(P2 + base) = v2;
    }
}

// ======================================================================
// GEMM: out[c][m] = sum_n V[c][n] * B[n][m]
//   TRANSB=false: B[n][m] = P[n][m]   (out_c = V * P2)
//   TRANSB=true : B[n][m] = P[m][n]   (out_b = V * P1^T)
// 64x64 block tile, BK=16, 4x4 microtile, 256 threads.
// ======================================================================
template<bool TRANSB>
__global__ __launch_bounds__(256) void gemm_vp_k(
    const float* __restrict__ V, const float* __restrict__ P,
    float* __restrict__ out)
{
    const int b  = blockIdx.z;
    const int c0 = blockIdx.y * 64;
    const int m0 = blockIdx.x * 64;
    const int tid = threadIdx.x;
    const int tx = tid & 15, ty = tid >> 4;

    __shared__ float As[16][64];
    __shared__ float Bs[16][64];

    const float* Vb = V + (size_t)b*NC*NN;
    const float* Pb = P + (size_t)b*NN*NN;

    float acc[4][4];
    #pragma unroll
    for (int i = 0; i < 4; i++)
        #pragma unroll
        for (int j = 0; j < 4; j++) acc[i][j] = 0.f;

    const int lr = tid >> 2;       // 0..63
    const int lc = tid & 3;        // 0..3 (float4 index)

    for (int k0 = 0; k0 < NN; k0 += 16) {
        {
            float4 v = *(const float4*)(Vb + (size_t)(c0+lr)*NN + k0 + lc*4);
            As[lc*4+0][lr] = v.x; As[lc*4+1][lr] = v.y;
            As[lc*4+2][lr] = v.z; As[lc*4+3][lr] = v.w;
        }
        if (TRANSB) {
            float4 v = *(const float4*)(Pb + (size_t)(m0+lr)*NN + k0 + lc*4);
            Bs[lc*4+0][lr] = v.x; Bs[lc*4+1][lr] = v.y;
            Bs[lc*4+2][lr] = v.z; Bs[lc*4+3][lr] = v.w;
        } else {
            int kk = tid >> 4, c4 = tid & 15;
            *(float4*)&Bs[kk][c4*4] = *(const float4*)(Pb + (size_t)(k0+kk)*NN + m0 + c4*4);
        }
        __syncthreads();

        #pragma unroll
        for (int k = 0; k < 16; k++) {
            float4 a  = *(const float4*)&As[k][ty*4];
            float4 bv = *(const float4*)&Bs[k][tx*4];
            float aa[4] = {a.x, a.y, a.z, a.w};
            float bb[4] = {bv.x, bv.y, bv.z, bv.w};
            #pragma unroll
            for (int i = 0; i < 4; i++)
                #pragma unroll
                for (int j = 0; j < 4; j++) acc[i][j] += aa[i]*bb[j];
        }
        __syncthreads();
    }

    #pragma unroll
    for (int i = 0; i < 4; i++) {
        float4 v = make_float4(acc[i][0], acc[i][1], acc[i][2], acc[i][3]);
        *(float4*)(out + (size_t)b*NC*NN + (size_t)(c0+ty*4+i)*NN + m0 + tx*4) = v;
    }
}

// ======================================================================
// SE layer pieces
// ======================================================================
__global__ __launch_bounds__(256) void se_reduce_k(
    const float* __restrict__ comp, float* __restrict__ y0)
{
    int b = blockIdx.y, c = blockIdx.x;
    const float* p = comp + ((size_t)b*NC + c)*NPIX;
    float s = 0.f;
    for (int i = threadIdx.x; i < NPIX; i += 256) s += p[i];
    #pragma unroll
    for (int o = 16; o; o >>= 1) s += __shfl_xor_sync(0xffffffffu, s, o);
    __shared__ float red[8];
    if ((threadIdx.x & 31) == 0) red[threadIdx.x >> 5] = s;
    __syncthreads();
    if (threadIdx.x == 0) {
        float t = 0.f;
        for (int i = 0; i < 8; i++) t += red[i];
        y0[b*NC + c] = t * (1.f / NPIX);
    }
}

__global__ __launch_bounds__(256) void se_mlp_k(
    const float* __restrict__ y0, const float* __restrict__ w1,
    const float* __restrict__ w2, float* __restrict__ se)
{
    int b = blockIdx.x, tid = threadIdx.x;
    __shared__ float ys[NC];
    __shared__ float hs[32];
    ys[tid] = y0[b*NC + tid];
    __syncthreads();
    if (tid < 32) {
        float a = 0.f;
        for (int j = 0; j < NC; j++) a += ys[j] * w1[tid*NC + j];
        hs[tid] = fmaxf(a, 0.f);
    }
    __syncthreads();
    float a = 0.f;
    #pragma unroll
    for (int j = 0; j < 32; j++) a += hs[j] * w2[tid*32 + j];
    se[b*NC + tid] = 1.f / (1.f + __expf(-a));
}

__global__ __launch_bounds__(256) void se_scale_k(
    const float* __restrict__ comp, const float* __restrict__ se,
    float* __restrict__ outA)
{
    size_t i = (size_t)blockIdx.x * 256 + threadIdx.x;
    if (i < (size_t)NB*NC*NPIX) {
        size_t bc = i >> 12;                 // / NPIX
        outA[i] = comp[i] * se[bc];
    }
}

// ======================================================================
// host launcher
// ======================================================================
template <typename T>
static float* symaddr(T& sym) {
    void* p = nullptr;
    cudaGetSymbolAddress(&p, sym);
    return (float*)p;
}

extern "C" void kernel_launch(void* const* d_in, const int* in_sizes, int n_in,
                              void* d_out, int out_size)
{
    const float* x      = (const float*)d_in[0];
    const float* mmask  = (const float*)d_in[1];
    const float* amask  = (const float*)d_in[2];
    const float* w_mp   = (const float*)d_in[3];
    const float* b_mp   = (const float*)d_in[4];
    const float* w_ap   = (const float*)d_in[5];
    const float* b_ap   = (const float*)d_in[6];
    const float* w_q    = (const float*)d_in[7];
    const float* b_q    = (const float*)d_in[8];
    const float* w_k    = (const float*)d_in[9];
    const float* b_k    = (const float*)d_in[10];
    const float* w_v    = (const float*)d_in[11];
    const float* b_v    = (const float*)d_in[12];
    const float* w_comp = (const float*)d_in[13];
    const float* b_comp = (const float*)d_in[14];
    const float* w_out  = (const float*)d_in[15];
    const float* b_out  = (const float*)d_in[16];
    const float* w_se1  = (const float*)d_in[17];
    const float* w_se2  = (const float*)d_in[18];
    float* out = (float*)d_out;

    float* modal  = symaddr(g_modal);
    float* amodal = symaddr(g_amodal);
    float* q      = symaddr(g_q);
    float* k      = symaddr(g_kk);
    float* v      = symaddr(g_v);
    float* comp   = symaddr(g_comp);
    float* outA   = symaddr(g_outA);
    float* outB   = symaddr(g_outB);
    float* outC   = symaddr(g_outC);
    float* P1     = symaddr(g_P1);
    float* P2     = symaddr(g_P2);
    float* rmax   = symaddr(g_rmax);
    float* rinv   = symaddr(g_rinv);
    float* cmax   = symaddr(g_cmax);
    float* cinv   = symaddr(g_cinv);
    float* y0     = symaddr(g_y0);
    float* se     = symaddr(g_se);

    const int BSX = NC*NPIX;      // x batch stride
    const int BSM = NCLS*NPIX;    // mask / modal batch stride
    const int BSQ = QKD*NPIX;

    // modal / amodal prediction convs (masked)
    conv3x3_k<<<dim3(4, 3, NB), 256>>>(x, NC, BSX, nullptr, 0, 0, nullptr, 0, 0,
                                       w_mp, b_mp, modal, BSM, NCLS, mmask, BSM);
    conv3x3_k<<<dim3(4, 3, NB), 256>>>(x, NC, BSX, nullptr, 0, 0, nullptr, 0, 0,
                                       w_ap, b_ap, amodal, BSM, NCLS, amask, BSM);

    // q/k/v convs
    conv3x3_k<<<dim3(4, 4, NB), 256>>>(x, NC, BSX, mmask, NCLS, BSM, nullptr, 0, 0,
                                       w_q, b_q, q, BSQ, QKD, nullptr, 0);
    conv3x3_k<<<dim3(4, 4, NB), 256>>>(x, NC, BSX, amask, NCLS, BSM, nullptr, 0, 0,
                                       w_k, b_k, k, BSQ, QKD, nullptr, 0);
    conv3x3_k<<<dim3(4, 32, NB), 256>>>(x, NC, BSX, nullptr, 0, 0, nullptr, 0, 0,
                                        w_v, b_v, v, BSX, NC, nullptr, 0);

    // comp conv over concat(x, modal_x, amodal_x)
    conv3x3_k<<<dim3(4, 32, NB), 256>>>(x, NC, BSX, modal, NCLS, BSM, amodal, NCLS, BSM,
                                        w_comp, b_comp, comp, BSX, NC, nullptr, 0);

    // SE layer -> out_a
    se_reduce_k<<<dim3(NC, NB), 256>>>(comp, y0);
    se_mlp_k<<<NB, 256>>>(y0, w_se1, w_se2, se);
    se_scale_k<<<(NB*NC*NPIX)/256, 256>>>(comp, se, outA);

    // attention stats: rows of E (q,k) and columns of E (k,q)
    attn_stats_k<<<dim3(NN/64, NB), 256>>>(q, k, rmax, rinv);
    attn_stats_k<<<dim3(NN/64, NB), 256>>>(k, q, cmax, cinv);

    // normalized softmax matrices
    attn_p_k<<<dim3(NN/64, NN/64, NB), 256>>>(q, k, rmax, rinv, cmax, cinv, P1, P2);

    // out_b = V * P1^T ; out_c = V * P2
    gemm_vp_k<true ><<<dim3(NN/64, NC/64, NB), 256>>>(v, P1, outB);
    gemm_vp_k<false><<<dim3(NN/64, NC/64, NB), 256>>>(v, P2, outC);

    // final conv over concat(out_a, out_b, out_c)
    conv3x3_k<<<dim3(4, 32, NB), 256>>>(outA, NC, BSX, outB, NC, BSX, outC, NC, BSX,
                                        w_out, b_out, out, BSX, NC, nullptr, 0);
}

// round 4
// speedup vs baseline: 1.4653x; 1.4653x over previous
#include <cuda_runtime.h>
#include <cstdint>

// ---------------- problem constants ----------------
#define NB   2
#define NC   256
#define HH   64
#define NPIX 4096           // 64*64
#define NN   4096           // attention sequence length
#define QKD  32
#define NCLS 19

// ---------------- scratch (device globals; no allocation allowed) ----------
__device__ float g_modal [NB*NCLS*NPIX];
__device__ float g_amodal[NB*NCLS*NPIX];
__device__ float g_q     [NB*QKD*NPIX];
__device__ float g_kk    [NB*QKD*NPIX];
__device__ float g_v     [(size_t)NB*NC*NPIX];
__device__ float g_comp  [(size_t)NB*NC*NPIX];
__device__ float g_outA  [(size_t)NB*NC*NPIX];
__device__ float g_outB  [(size_t)NB*NC*NPIX];
__device__ float g_outC  [(size_t)NB*NC*NPIX];
__device__ float g_P1    [(size_t)NB*NN*NN];
__device__ float g_P2    [(size_t)NB*NN*NN];
__device__ float g_rmax  [NB*NN];
__device__ float g_rinv  [NB*NN];
__device__ float g_cmax  [NB*NN];
__device__ float g_cinv  [NB*NN];
__device__ float g_y0    [NB*NC];
__device__ float g_se    [NB*NC];
// K-split partial accumulators: up to 4 chunks x NB x 32oc x NPIX
__device__ float g_part  [4*NB*32*NPIX];

// ======================================================================
// Generic 3x3 SAME conv, NCHW, input = concat of up to 3 channel segments.
// Block: 256 threads, 32x32 spatial tile, 8 output channels, 4 px/thread.
// Stages IC_STEP=4 input channels per barrier (latency amortization).
// Optional K-split across blockIdx.y (writes partial sums, no bias/mask).
// ======================================================================
#define IC_STEP 4

__global__ __launch_bounds__(256, 2) void conv3x3_k(
    const float* __restrict__ p0, int c0, int bs0,
    const float* __restrict__ p1, int c1, int bs1,
    const float* __restrict__ p2, int c2, int bs2,
    const float* __restrict__ wt,    // [Cout][Cin][3][3]
    const float* __restrict__ bias,  // [Cout]
    float* __restrict__ out, int outBS, int Cout, int nOcg,
    const float* __restrict__ mask, int maskBS,
    int kChunks, int chunkSize,
    float* __restrict__ partial)
{
    const int Cin = c0 + c1 + c2;
    const int tileIdx = blockIdx.x;            // 0..3
    const int ty0 = (tileIdx >> 1) * 32;
    const int tx0 = (tileIdx &  1) * 32;
    const int kchunk = blockIdx.y / nOcg;
    const int ocg    = (blockIdx.y - kchunk*nOcg) * 8;
    const int b   = blockIdx.z;

    const int icStart = kchunk * chunkSize;
    int icEnd = icStart + chunkSize;
    if (icEnd > Cin) icEnd = Cin;

    const int tid = threadIdx.x;
    const int tx  = tid & 31;
    const int ty  = tid >> 5;                  // 0..7

    __shared__ float in_s[IC_STEP][34*34];
    __shared__ float ws[IC_STEP*72];

    float acc[4][8];
    #pragma unroll
    for (int p = 0; p < 4; p++)
        #pragma unroll
        for (int o = 0; o < 8; o++) acc[p][o] = 0.f;

    for (int icBase = icStart; icBase < icEnd; icBase += IC_STEP) {
        __syncthreads();
        // load up to IC_STEP input-channel tiles
        #pragma unroll
        for (int c = 0; c < IC_STEP; c++) {
            int ic = icBase + c;
            if (ic >= icEnd) break;
            const float* src;
            if (ic < c0)           src = p0 + (size_t)b*bs0 + (size_t)ic        *NPIX;
            else if (ic < c0+c1)   src = p1 + (size_t)b*bs1 + (size_t)(ic-c0)   *NPIX;
            else                   src = p2 + (size_t)b*bs2 + (size_t)(ic-c0-c1)*NPIX;
            for (int i = tid; i < 34*34; i += 256) {
                int r = i / 34, cc = i - r*34;
                int yy = ty0 + r - 1, xx = tx0 + cc - 1;
                float v = 0.f;
                if (yy >= 0 && yy < HH && xx >= 0 && xx < HH) v = src[yy*HH + xx];
                in_s[c][i] = v;
            }
        }
        // weights: ws[c][o][t]
        for (int j = tid; j < IC_STEP*72; j += 256) {
            int c = j / 72, rem = j - c*72;
            int o = rem / 9, t = rem - o*9;
            int ic = icBase + c;
            float wv = 0.f;
            if (ic < icEnd && ocg + o < Cout)
                wv = wt[((size_t)(ocg+o)*Cin + ic)*9 + t];
            ws[j] = wv;
        }
        __syncthreads();

        #pragma unroll
        for (int c = 0; c < IC_STEP; c++) {
            float win[4][9];
            #pragma unroll
            for (int p = 0; p < 4; p++) {
                int py = ty + p*8;
                #pragma unroll
                for (int dy = 0; dy < 3; dy++)
                    #pragma unroll
                    for (int dx = 0; dx < 3; dx++)
                        win[p][dy*3+dx] = in_s[c][(py+dy)*34 + tx+dx];
            }
            #pragma unroll
            for (int o = 0; o < 8; o++) {
                #pragma unroll
                for (int t = 0; t < 9; t++) {
                    float wv = ws[c*72 + o*9 + t];
                    #pragma unroll
                    for (int p = 0; p < 4; p++) acc[p][o] += wv * win[p][t];
                }
            }
        }
    }

    if (kChunks > 1) {
        // partial write (no bias, no mask)
        const size_t stride = (size_t)NB*Cout*NPIX;
        #pragma unroll
        for (int o = 0; o < 8; o++) {
            int oc = ocg + o;
            if (oc >= Cout) break;
            #pragma unroll
            for (int p = 0; p < 4; p++) {
                int py = ty0 + ty + p*8;
                int px = tx0 + tx;
                size_t pix = (size_t)py*HH + px;
                partial[(size_t)kchunk*stride + ((size_t)b*Cout + oc)*NPIX + pix] = acc[p][o];
            }
        }
    } else {
        #pragma unroll
        for (int o = 0; o < 8; o++) {
            int oc = ocg + o;
            if (oc >= Cout) break;
            float bv = bias ? bias[oc] : 0.f;
            #pragma unroll
            for (int p = 0; p < 4; p++) {
                int py = ty0 + ty + p*8;
                int px = tx0 + tx;
                size_t pix = (size_t)py*HH + px;
                float v = acc[p][o] + bv;
                if (mask) v *= mask[(size_t)b*maskBS + (size_t)oc*NPIX + pix];
                out[(size_t)b*outBS + (size_t)oc*NPIX + pix] = v;
            }
        }
    }
}

// combine K-split partials: sum chunks, add bias, optional mask multiply
__global__ __launch_bounds__(256) void conv_combine_k(
    const float* __restrict__ partial, int kChunks,
    const float* __restrict__ bias,
    float* __restrict__ out, int outBS, int Cout,
    const float* __restrict__ mask, int maskBS)
{
    const size_t total = (size_t)NB*Cout*NPIX;
    size_t i = (size_t)blockIdx.x*256 + threadIdx.x;
    if (i >= total) return;
    const size_t cp = (size_t)Cout*NPIX;
    int b = (int)(i / cp);
    size_t within = i - (size_t)b*cp;
    int oc = (int)(within >> 12);
    const size_t stride = (size_t)NB*Cout*NPIX;
    float s = bias[oc];
    for (int ch = 0; ch < kChunks; ch++) s += partial[ch*stride + i];
    if (mask) s *= mask[(size_t)b*maskBS + within];
    out[(size_t)b*outBS + within] = s;
}

// ======================================================================
// Flash-style softmax stats over rows of E = Q^T K  (Q,K: [B][32][N]).
// ======================================================================
__global__ __launch_bounds__(256) void attn_stats_k(
    const float* __restrict__ Q, const float* __restrict__ K,
    float* __restrict__ omax, float* __restrict__ oinv)
{
    const int b  = blockIdx.y;
    const int n0 = blockIdx.x * 64;
    const int tid = threadIdx.x;
    const int tx = tid & 15, ty = tid >> 4;

    __shared__ float qs[32][64];
    __shared__ float ks[32][64];
    __shared__ float redM[64][17];
    __shared__ float redS[64][17];

    const float* qb = Q + (size_t)b*QKD*NN;
    const float* kb = K + (size_t)b*QKD*NN;

    for (int i = tid; i < 32*16; i += 256) {
        int d = i >> 4, c4 = i & 15;
        *(float4*)&qs[d][c4*4] = *(const float4*)(qb + (size_t)d*NN + n0 + c4*4);
    }

    float M[4], S[4];
    #pragma unroll
    for (int i = 0; i < 4; i++) { M[i] = -1e30f; S[i] = 0.f; }

    for (int m0 = 0; m0 < NN; m0 += 64) {
        __syncthreads();
        for (int i = tid; i < 32*16; i += 256) {
            int d = i >> 4, c4 = i & 15;
            *(float4*)&ks[d][c4*4] = *(const float4*)(kb + (size_t)d*NN + m0 + c4*4);
        }
        __syncthreads();

        float e[4][4];
        #pragma unroll
        for (int i = 0; i < 4; i++)
            #pragma unroll
            for (int j = 0; j < 4; j++) e[i][j] = 0.f;

        #pragma unroll
        for (int d = 0; d < 32; d++) {
            float4 a  = *(const float4*)&qs[d][ty*4];
            float4 bv = *(const float4*)&ks[d][tx*4];
            float aa[4] = {a.x, a.y, a.z, a.w};
            float bb[4] = {bv.x, bv.y, bv.z, bv.w};
            #pragma unroll
            for (int i = 0; i < 4; i++)
                #pragma unroll
                for (int j = 0; j < 4; j++) e[i][j] += aa[i]*bb[j];
        }
        #pragma unroll
        for (int i = 0; i < 4; i++) {
            float lm = fmaxf(fmaxf(e[i][0], e[i][1]), fmaxf(e[i][2], e[i][3]));
            float nm = fmaxf(M[i], lm);
            float s = S[i] * __expf(M[i] - nm);
            #pragma unroll
            for (int j = 0; j < 4; j++) s += __expf(e[i][j] - nm);
            M[i] = nm; S[i] = s;
        }
    }
    __syncthreads();
    #pragma unroll
    for (int i = 0; i < 4; i++) { redM[ty*4+i][tx] = M[i]; redS[ty*4+i][tx] = S[i]; }
    __syncthreads();
    if (tid < 64) {
        float m = redM[tid][0], s = redS[tid][0];
        for (int j = 1; j < 16; j++) {
            float m2 = redM[tid][j], s2 = redS[tid][j];
            float nm = fmaxf(m, m2);
            s = s*__expf(m - nm) + s2*__expf(m2 - nm);
            m = nm;
        }
        omax[(size_t)b*NN + n0 + tid] = m;
        oinv[(size_t)b*NN + n0 + tid] = 1.f / s;
    }
}

// ======================================================================
// P kernel: compute E tile once, write both normalized softmax matrices.
// ======================================================================
__global__ __launch_bounds__(256) void attn_p_k(
    const float* __restrict__ Q, const float* __restrict__ K,
    const float* __restrict__ rmax, const float* __restrict__ rinv,
    const float* __restrict__ cmax, const float* __restrict__ cinv,
    float* __restrict__ P1, float* __restrict__ P2)
{
    const int b  = blockIdx.z;
    const int n0 = blockIdx.y * 64;
    const int m0 = blockIdx.x * 64;
    const int tid = threadIdx.x;
    const int tx = tid & 15, ty = tid >> 4;

    __shared__ float qs[32][64];
    __shared__ float ks[32][64];

    const float* qb = Q + (size_t)b*QKD*NN;
    const float* kb = K + (size_t)b*QKD*NN;

    for (int i = tid; i < 32*16; i += 256) {
        int d = i >> 4, c4 = i & 15;
        *(float4*)&qs[d][c4*4] = *(const float4*)(qb + (size_t)d*NN + n0 + c4*4);
        *(float4*)&ks[d][c4*4] = *(const float4*)(kb + (size_t)d*NN + m0 + c4*4);
    }
    __syncthreads();

    float e[4][4];
    #pragma unroll
    for (int i = 0; i < 4; i++)
        #pragma unroll
        for (int j = 0; j < 4; j++) e[i][j] = 0.f;

    #pragma unroll
    for (int d = 0; d < 32; d++) {
        float4 a  = *(const float4*)&qs[d][ty*4];
        float4 bv = *(const float4*)&ks[d][tx*4];
        float aa[4] = {a.x, a.y, a.z, a.w};
        float bb[4] = {bv.x, bv.y, bv.z, bv.w};
        #pragma unroll
        for (int i = 0; i < 4; i++)
            #pragma unroll
            for (int j = 0; j < 4; j++) e[i][j] += aa[i]*bb[j];
    }

    float rm[4], ri[4], cm[4], ci[4];
    #pragma unroll
    for (int i = 0; i < 4; i++) {
        rm[i] = rmax[(size_t)b*NN + n0 + ty*4 + i];
        ri[i] = rinv[(size_t)b*NN + n0 + ty*4 + i];
        cm[i] = cmax[(size_t)b*NN + m0 + tx*4 + i];
        ci[i] = cinv[(size_t)b*NN + m0 + tx*4 + i];
    }

    #pragma unroll
    for (int i = 0; i < 4; i++) {
        int n = n0 + ty*4 + i;
        float4 v1, v2;
        float* pv1 = (float*)&v1;
        float* pv2 = (float*)&v2;
        #pragma unroll
        for (int j = 0; j < 4; j++) {
            pv1[j] = __expf(e[i][j] - rm[i]) * ri[i];
            pv2[j] = __expf(e[i][j] - cm[j]) * ci[j];
        }
        size_t base = (size_t)b*NN*NN + (size_t)n*NN + m0 + tx*4;
        *(float4*)(P1 + base) = v1;
        *(float4*)(P2 + base) = v2;
    }
}

// ======================================================================
// GEMM: out[c][m] = sum_n V[c][n] * B[n][m]
// ======================================================================
template<bool TRANSB>
__global__ __launch_bounds__(256) void gemm_vp_k(
    const float* __restrict__ V, const float* __restrict__ P,
    float* __restrict__ out)
{
    const int b  = blockIdx.z;
    const int c0 = blockIdx.y * 64;
    const int m0 = blockIdx.x * 64;
    const int tid = threadIdx.x;
    const int tx = tid & 15, ty = tid >> 4;

    __shared__ float As[16][64];
    __shared__ float Bs[16][64];

    const float* Vb = V + (size_t)b*NC*NN;
    const float* Pb = P + (size_t)b*NN*NN;

    float acc[4][4];
    #pragma unroll
    for (int i = 0; i < 4; i++)
        #pragma unroll
        for (int j = 0; j < 4; j++) acc[i][j] = 0.f;

    const int lr = tid >> 2;       // 0..63
    const int lc = tid & 3;        // 0..3 (float4 index)

    for (int k0 = 0; k0 < NN; k0 += 16) {
        {
            float4 v = *(const float4*)(Vb + (size_t)(c0+lr)*NN + k0 + lc*4);
            As[lc*4+0][lr] = v.x; As[lc*4+1][lr] = v.y;
            As[lc*4+2][lr] = v.z; As[lc*4+3][lr] = v.w;
        }
        if (TRANSB) {
            float4 v = *(const float4*)(Pb + (size_t)(m0+lr)*NN + k0 + lc*4);
            Bs[lc*4+0][lr] = v.x; Bs[lc*4+1][lr] = v.y;
            Bs[lc*4+2][lr] = v.z; Bs[lc*4+3][lr] = v.w;
        } else {
            int kk = tid >> 4, c4 = tid & 15;
            *(float4*)&Bs[kk][c4*4] = *(const float4*)(Pb + (size_t)(k0+kk)*NN + m0 + c4*4);
        }
        __syncthreads();

        #pragma unroll
        for (int k = 0; k < 16; k++) {
            float4 a  = *(const float4*)&As[k][ty*4];
            float4 bv = *(const float4*)&Bs[k][tx*4];
            float aa[4] = {a.x, a.y, a.z, a.w};
            float bb[4] = {bv.x, bv.y, bv.z, bv.w};
            #pragma unroll
            for (int i = 0; i < 4; i++)
                #pragma unroll
                for (int j = 0; j < 4; j++) acc[i][j] += aa[i]*bb[j];
        }
        __syncthreads();
    }

    #pragma unroll
    for (int i = 0; i < 4; i++) {
        float4 v = make_float4(acc[i][0], acc[i][1], acc[i][2], acc[i][3]);
        *(float4*)(out + (size_t)b*NC*NN + (size_t)(c0+ty*4+i)*NN + m0 + tx*4) = v;
    }
}

// ======================================================================
// SE layer pieces
// ======================================================================
__global__ __launch_bounds__(256) void se_reduce_k(
    const float* __restrict__ comp, float* __restrict__ y0)
{
    int b = blockIdx.y, c = blockIdx.x;
    const float* p = comp + ((size_t)b*NC + c)*NPIX;
    float s = 0.f;
    for (int i = threadIdx.x; i < NPIX; i += 256) s += p[i];
    #pragma unroll
    for (int o = 16; o; o >>= 1) s += __shfl_xor_sync(0xffffffffu, s, o);
    __shared__ float red[8];
    if ((threadIdx.x & 31) == 0) red[threadIdx.x >> 5] = s;
    __syncthreads();
    if (threadIdx.x == 0) {
        float t = 0.f;
        for (int i = 0; i < 8; i++) t += red[i];
        y0[b*NC + c] = t * (1.f / NPIX);
    }
}

__global__ __launch_bounds__(256) void se_mlp_k(
    const float* __restrict__ y0, const float* __restrict__ w1,
    const float* __restrict__ w2, float* __restrict__ se)
{
    int b = blockIdx.x, tid = threadIdx.x;
    __shared__ float ys[NC];
    __shared__ float hs[32];
    ys[tid] = y0[b*NC + tid];
    __syncthreads();
    if (tid < 32) {
        float a = 0.f;
        for (int j = 0; j < NC; j++) a += ys[j] * w1[tid*NC + j];
        hs[tid] = fmaxf(a, 0.f);
    }
    __syncthreads();
    float a = 0.f;
    #pragma unroll
    for (int j = 0; j < 32; j++) a += hs[j] * w2[tid*32 + j];
    se[b*NC + tid] = 1.f / (1.f + __expf(-a));
}

__global__ __launch_bounds__(256) void se_scale_k(
    const float* __restrict__ comp, const float* __restrict__ se,
    float* __restrict__ outA)
{
    size_t i = (size_t)blockIdx.x * 256 + threadIdx.x;
    if (i < (size_t)NB*NC*NPIX) {
        size_t bc = i >> 12;                 // / NPIX
        outA[i] = comp[i] * se[bc];
    }
}

// ======================================================================
// host launcher
// ======================================================================
template <typename T>
static float* symaddr(T& sym) {
    void* p = nullptr;
    cudaGetSymbolAddress(&p, sym);
    return (float*)p;
}

extern "C" void kernel_launch(void* const* d_in, const int* in_sizes, int n_in,
                              void* d_out, int out_size)
{
    const float* x      = (const float*)d_in[0];
    const float* mmask  = (const float*)d_in[1];
    const float* amask  = (const float*)d_in[2];
    const float* w_mp   = (const float*)d_in[3];
    const float* b_mp   = (const float*)d_in[4];
    const float* w_ap   = (const float*)d_in[5];
    const float* b_ap   = (const float*)d_in[6];
    const float* w_q    = (const float*)d_in[7];
    const float* b_q    = (const float*)d_in[8];
    const float* w_k    = (const float*)d_in[9];
    const float* b_k    = (const float*)d_in[10];
    const float* w_v    = (const float*)d_in[11];
    const float* b_v    = (const float*)d_in[12];
    const float* w_comp = (const float*)d_in[13];
    const float* b_comp = (const float*)d_in[14];
    const float* w_out  = (const float*)d_in[15];
    const float* b_out  = (const float*)d_in[16];
    const float* w_se1  = (const float*)d_in[17];
    const float* w_se2  = (const float*)d_in[18];
    float* out = (float*)d_out;

    float* modal  = symaddr(g_modal);
    float* amodal = symaddr(g_amodal);
    float* q      = symaddr(g_q);
    float* k      = symaddr(g_kk);
    float* v      = symaddr(g_v);
    float* comp   = symaddr(g_comp);
    float* outA   = symaddr(g_outA);
    float* outB   = symaddr(g_outB);
    float* outC   = symaddr(g_outC);
    float* P1     = symaddr(g_P1);
    float* P2     = symaddr(g_P2);
    float* rmax   = symaddr(g_rmax);
    float* rinv   = symaddr(g_rinv);
    float* cmax   = symaddr(g_cmax);
    float* cinv   = symaddr(g_cinv);
    float* y0     = symaddr(g_y0);
    float* se     = symaddr(g_se);
    float* part   = symaddr(g_part);

    const int BSX = NC*NPIX;      // x batch stride
    const int BSM = NCLS*NPIX;    // mask / modal batch stride
    const int BSQ = QKD*NPIX;

    // ---- modal prediction conv (K-split x4, masked combine) ----
    conv3x3_k<<<dim3(4, 3*4, NB), 256>>>(x, NC, BSX, nullptr,0,0, nullptr,0,0,
        w_mp, b_mp, modal, BSM, NCLS, 3, nullptr, 0, 4, 64, part);
    conv_combine_k<<<(NB*NCLS*NPIX + 255)/256, 256>>>(part, 4, b_mp, modal, BSM, NCLS, mmask, BSM);

    // ---- amodal prediction conv ----
    conv3x3_k<<<dim3(4, 3*4, NB), 256>>>(x, NC, BSX, nullptr,0,0, nullptr,0,0,
        w_ap, b_ap, amodal, BSM, NCLS, 3, nullptr, 0, 4, 64, part);
    conv_combine_k<<<(NB*NCLS*NPIX + 255)/256, 256>>>(part, 4, b_ap, amodal, BSM, NCLS, amask, BSM);

    // ---- q conv (Cin=275, K-split x4) ----
    conv3x3_k<<<dim3(4, 4*4, NB), 256>>>(x, NC, BSX, mmask, NCLS, BSM, nullptr,0,0,
        w_q, b_q, q, BSQ, QKD, 4, nullptr, 0, 4, 69, part);
    conv_combine_k<<<(NB*QKD*NPIX + 255)/256, 256>>>(part, 4, b_q, q, BSQ, QKD, nullptr, 0);

    // ---- k conv ----
    conv3x3_k<<<dim3(4, 4*4, NB), 256>>>(x, NC, BSX, amask, NCLS, BSM, nullptr,0,0,
        w_k, b_k, k, BSQ, QKD, 4, nullptr, 0, 4, 69, part);
    conv_combine_k<<<(NB*QKD*NPIX + 255)/256, 256>>>(part, 4, b_k, k, BSQ, QKD, nullptr, 0);

    // ---- v conv (direct) ----
    conv3x3_k<<<dim3(4, 32, NB), 256>>>(x, NC, BSX, nullptr,0,0, nullptr,0,0,
        w_v, b_v, v, BSX, NC, 32, nullptr, 0, 1, NC, nullptr);

    // ---- comp conv over concat(x, modal_x, amodal_x) ----
    conv3x3_k<<<dim3(4, 32, NB), 256>>>(x, NC, BSX, modal, NCLS, BSM, amodal, NCLS, BSM,
        w_comp, b_comp, comp, BSX, NC, 32, nullptr, 0, 1, NC + 2*NCLS, nullptr);

    // ---- SE layer -> out_a ----
    se_reduce_k<<<dim3(NC, NB), 256>>>(comp, y0);
    se_mlp_k<<<NB, 256>>>(y0, w_se1, w_se2, se);
    se_scale_k<<<(NB*NC*NPIX)/256, 256>>>(comp, se, outA);

    // ---- attention stats: rows of E (q,k) and columns of E (k,q) ----
    attn_stats_k<<<dim3(NN/64, NB), 256>>>(q, k, rmax, rinv);
    attn_stats_k<<<dim3(NN/64, NB), 256>>>(k, q, cmax, cinv);

    // ---- normalized softmax matrices ----
    attn_p_k<<<dim3(NN/64, NN/64, NB), 256>>>(q, k, rmax, rinv, cmax, cinv, P1, P2);

    // ---- out_b = V * P1^T ; out_c = V * P2 ----
    gemm_vp_k<true ><<<dim3(NN/64, NC/64, NB), 256>>>(v, P1, outB);
    gemm_vp_k<false><<<dim3(NN/64, NC/64, NB), 256>>>(v, P2, outC);

    // ---- final conv over concat(out_a, out_b, out_c) ----
    conv3x3_k<<<dim3(4, 32, NB), 256>>>(outA, NC, BSX, outB, NC, BSX, outC, NC, BSX,
        w_out, b_out, out, BSX, NC, 32, nullptr, 0, 1, 3*NC, nullptr);
}

// round 5
// speedup vs baseline: 1.7738x; 1.2105x over previous
#include <cuda_runtime.h>
#include <cstdint>

// ---------------- problem constants ----------------
#define NB   2
#define NC   256
#define HH   64
#define NPIX 4096           // 64*64
#define NN   4096           // attention sequence length
#define QKD  32
#define NCLS 19

// ---------------- scratch (device globals; no allocation allowed) ----------
__device__ float g_modal [NB*NCLS*NPIX];
__device__ float g_amodal[NB*NCLS*NPIX];
__device__ float g_q     [NB*QKD*NPIX];
__device__ float g_kk    [NB*QKD*NPIX];
__device__ float g_v     [(size_t)NB*NC*NPIX];
__device__ float g_comp  [(size_t)NB*NC*NPIX];
__device__ float g_outA  [(size_t)NB*NC*NPIX];
__device__ float g_outB  [(size_t)NB*NC*NPIX];
__device__ float g_outC  [(size_t)NB*NC*NPIX];
__device__ float g_P1    [(size_t)NB*NN*NN];
__device__ float g_P2    [(size_t)NB*NN*NN];
__device__ float g_rmax  [NB*NN];
__device__ float g_rinv  [NB*NN];
__device__ float g_cmax  [NB*NN];
__device__ float g_cinv  [NB*NN];
__device__ float g_y0    [NB*NC];
__device__ float g_se    [NB*NC];
// K-split partial accumulators: up to 4 chunks x NB x 32oc x NPIX
__device__ float g_part  [4*NB*32*NPIX];

// ======================================================================
// Generic 3x3 SAME conv, NCHW, input = concat of up to 3 channel segments.
// ======================================================================
#define IC_STEP 4

__global__ __launch_bounds__(256, 2) void conv3x3_k(
    const float* __restrict__ p0, int c0, int bs0,
    const float* __restrict__ p1, int c1, int bs1,
    const float* __restrict__ p2, int c2, int bs2,
    const float* __restrict__ wt,    // [Cout][Cin][3][3]
    const float* __restrict__ bias,  // [Cout]
    float* __restrict__ out, int outBS, int Cout, int nOcg,
    const float* __restrict__ mask, int maskBS,
    int kChunks, int chunkSize,
    float* __restrict__ partial)
{
    const int Cin = c0 + c1 + c2;
    const int tileIdx = blockIdx.x;            // 0..3
    const int ty0 = (tileIdx >> 1) * 32;
    const int tx0 = (tileIdx &  1) * 32;
    const int kchunk = blockIdx.y / nOcg;
    const int ocg    = (blockIdx.y - kchunk*nOcg) * 8;
    const int b   = blockIdx.z;

    const int icStart = kchunk * chunkSize;
    int icEnd = icStart + chunkSize;
    if (icEnd > Cin) icEnd = Cin;

    const int tid = threadIdx.x;
    const int tx  = tid & 31;
    const int ty  = tid >> 5;                  // 0..7

    __shared__ float in_s[IC_STEP][34*34];
    __shared__ float ws[IC_STEP*72];

    float acc[4][8];
    #pragma unroll
    for (int p = 0; p < 4; p++)
        #pragma unroll
        for (int o = 0; o < 8; o++) acc[p][o] = 0.f;

    for (int icBase = icStart; icBase < icEnd; icBase += IC_STEP) {
        __syncthreads();
        #pragma unroll
        for (int c = 0; c < IC_STEP; c++) {
            int ic = icBase + c;
            if (ic >= icEnd) break;
            const float* src;
            if (ic < c0)           src = p0 + (size_t)b*bs0 + (size_t)ic        *NPIX;
            else if (ic < c0+c1)   src = p1 + (size_t)b*bs1 + (size_t)(ic-c0)   *NPIX;
            else                   src = p2 + (size_t)b*bs2 + (size_t)(ic-c0-c1)*NPIX;
            for (int i = tid; i < 34*34; i += 256) {
                int r = i / 34, cc = i - r*34;
                int yy = ty0 + r - 1, xx = tx0 + cc - 1;
                float v = 0.f;
                if (yy >= 0 && yy < HH && xx >= 0 && xx < HH) v = src[yy*HH + xx];
                in_s[c][i] = v;
            }
        }
        for (int j = tid; j < IC_STEP*72; j += 256) {
            int c = j / 72, rem = j - c*72;
            int o = rem / 9, t = rem - o*9;
            int ic = icBase + c;
            float wv = 0.f;
            if (ic < icEnd && ocg + o < Cout)
                wv = wt[((size_t)(ocg+o)*Cin + ic)*9 + t];
            ws[j] = wv;
        }
        __syncthreads();

        #pragma unroll
        for (int c = 0; c < IC_STEP; c++) {
            float win[4][9];
            #pragma unroll
            for (int p = 0; p < 4; p++) {
                int py = ty + p*8;
                #pragma unroll
                for (int dy = 0; dy < 3; dy++)
                    #pragma unroll
                    for (int dx = 0; dx < 3; dx++)
                        win[p][dy*3+dx] = in_s[c][(py+dy)*34 + tx+dx];
            }
            #pragma unroll
            for (int o = 0; o < 8; o++) {
                #pragma unroll
                for (int t = 0; t < 9; t++) {
                    float wv = ws[c*72 + o*9 + t];
                    #pragma unroll
                    for (int p = 0; p < 4; p++) acc[p][o] += wv * win[p][t];
                }
            }
        }
    }

    if (kChunks > 1) {
        const size_t stride = (size_t)NB*Cout*NPIX;
        #pragma unroll
        for (int o = 0; o < 8; o++) {
            int oc = ocg + o;
            if (oc >= Cout) break;
            #pragma unroll
            for (int p = 0; p < 4; p++) {
                int py = ty0 + ty + p*8;
                int px = tx0 + tx;
                size_t pix = (size_t)py*HH + px;
                partial[(size_t)kchunk*stride + ((size_t)b*Cout + oc)*NPIX + pix] = acc[p][o];
            }
        }
    } else {
        #pragma unroll
        for (int o = 0; o < 8; o++) {
            int oc = ocg + o;
            if (oc >= Cout) break;
            float bv = bias ? bias[oc] : 0.f;
            #pragma unroll
            for (int p = 0; p < 4; p++) {
                int py = ty0 + ty + p*8;
                int px = tx0 + tx;
                size_t pix = (size_t)py*HH + px;
                float v = acc[p][o] + bv;
                if (mask) v *= mask[(size_t)b*maskBS + (size_t)oc*NPIX + pix];
                out[(size_t)b*outBS + (size_t)oc*NPIX + pix] = v;
            }
        }
    }
}

// combine K-split partials
__global__ __launch_bounds__(256) void conv_combine_k(
    const float* __restrict__ partial, int kChunks,
    const float* __restrict__ bias,
    float* __restrict__ out, int outBS, int Cout,
    const float* __restrict__ mask, int maskBS)
{
    const size_t total = (size_t)NB*Cout*NPIX;
    size_t i = (size_t)blockIdx.x*256 + threadIdx.x;
    if (i >= total) return;
    const size_t cp = (size_t)Cout*NPIX;
    int b = (int)(i / cp);
    size_t within = i - (size_t)b*cp;
    int oc = (int)(within >> 12);
    const size_t stride = (size_t)NB*Cout*NPIX;
    float s = bias[oc];
    for (int ch = 0; ch < kChunks; ch++) s += partial[ch*stride + i];
    if (mask) s *= mask[(size_t)b*maskBS + within];
    out[(size_t)b*outBS + within] = s;
}

// ======================================================================
// Flash-style softmax stats over rows of E = Q^T K
// ======================================================================
__global__ __launch_bounds__(256) void attn_stats_k(
    const float* __restrict__ Q, const float* __restrict__ K,
    float* __restrict__ omax, float* __restrict__ oinv)
{
    const int b  = blockIdx.y;
    const int n0 = blockIdx.x * 64;
    const int tid = threadIdx.x;
    const int tx = tid & 15, ty = tid >> 4;

    __shared__ float qs[32][64];
    __shared__ float ks[32][64];
    __shared__ float redM[64][17];
    __shared__ float redS[64][17];

    const float* qb = Q + (size_t)b*QKD*NN;
    const float* kb = K + (size_t)b*QKD*NN;

    for (int i = tid; i < 32*16; i += 256) {
        int d = i >> 4, c4 = i & 15;
        *(float4*)&qs[d][c4*4] = *(const float4*)(qb + (size_t)d*NN + n0 + c4*4);
    }

    float M[4], S[4];
    #pragma unroll
    for (int i = 0; i < 4; i++) { M[i] = -1e30f; S[i] = 0.f; }

    for (int m0 = 0; m0 < NN; m0 += 64) {
        __syncthreads();
        for (int i = tid; i < 32*16; i += 256) {
            int d = i >> 4, c4 = i & 15;
            *(float4*)&ks[d][c4*4] = *(const float4*)(kb + (size_t)d*NN + m0 + c4*4);
        }
        __syncthreads();

        float e[4][4];
        #pragma unroll
        for (int i = 0; i < 4; i++)
            #pragma unroll
            for (int j = 0; j < 4; j++) e[i][j] = 0.f;

        #pragma unroll
        for (int d = 0; d < 32; d++) {
            float4 a  = *(const float4*)&qs[d][ty*4];
            float4 bv = *(const float4*)&ks[d][tx*4];
            float aa[4] = {a.x, a.y, a.z, a.w};
            float bb[4] = {bv.x, bv.y, bv.z, bv.w};
            #pragma unroll
            for (int i = 0; i < 4; i++)
                #pragma unroll
                for (int j = 0; j < 4; j++) e[i][j] += aa[i]*bb[j];
        }
        #pragma unroll
        for (int i = 0; i < 4; i++) {
            float lm = fmaxf(fmaxf(e[i][0], e[i][1]), fmaxf(e[i][2], e[i][3]));
            float nm = fmaxf(M[i], lm);
            float s = S[i] * __expf(M[i] - nm);
            #pragma unroll
            for (int j = 0; j < 4; j++) s += __expf(e[i][j] - nm);
            M[i] = nm; S[i] = s;
        }
    }
    __syncthreads();
    #pragma unroll
    for (int i = 0; i < 4; i++) { redM[ty*4+i][tx] = M[i]; redS[ty*4+i][tx] = S[i]; }
    __syncthreads();
    if (tid < 64) {
        float m = redM[tid][0], s = redS[tid][0];
        for (int j = 1; j < 16; j++) {
            float m2 = redM[tid][j], s2 = redS[tid][j];
            float nm = fmaxf(m, m2);
            s = s*__expf(m - nm) + s2*__expf(m2 - nm);
            m = nm;
        }
        omax[(size_t)b*NN + n0 + tid] = m;
        oinv[(size_t)b*NN + n0 + tid] = 1.f / s;
    }
}

// ======================================================================
// P kernel: compute E tile once, write both normalized softmax matrices.
// ======================================================================
__global__ __launch_bounds__(256) void attn_p_k(
    const float* __restrict__ Q, const float* __restrict__ K,
    const float* __restrict__ rmax, const float* __restrict__ rinv,
    const float* __restrict__ cmax, const float* __restrict__ cinv,
    float* __restrict__ P1, float* __restrict__ P2)
{
    const int b  = blockIdx.z;
    const int n0 = blockIdx.y * 64;
    const int m0 = blockIdx.x * 64;
    const int tid = threadIdx.x;
    const int tx = tid & 15, ty = tid >> 4;

    __shared__ float qs[32][64];
    __shared__ float ks[32][64];

    const float* qb = Q + (size_t)b*QKD*NN;
    const float* kb = K + (size_t)b*QKD*NN;

    for (int i = tid; i < 32*16; i += 256) {
        int d = i >> 4, c4 = i & 15;
        *(float4*)&qs[d][c4*4] = *(const float4*)(qb + (size_t)d*NN + n0 + c4*4);
        *(float4*)&ks[d][c4*4] = *(const float4*)(kb + (size_t)d*NN + m0 + c4*4);
    }
    __syncthreads();

    float e[4][4];
    #pragma unroll
    for (int i = 0; i < 4; i++)
        #pragma unroll
        for (int j = 0; j < 4; j++) e[i][j] = 0.f;

    #pragma unroll
    for (int d = 0; d < 32; d++) {
        float4 a  = *(const float4*)&qs[d][ty*4];
        float4 bv = *(const float4*)&ks[d][tx*4];
        float aa[4] = {a.x, a.y, a.z, a.w};
        float bb[4] = {bv.x, bv.y, bv.z, bv.w};
        #pragma unroll
        for (int i = 0; i < 4; i++)
            #pragma unroll
            for (int j = 0; j < 4; j++) e[i][j] += aa[i]*bb[j];
    }

    float rm[4], ri[4], cm[4], ci[4];
    #pragma unroll
    for (int i = 0; i < 4; i++) {
        rm[i] = rmax[(size_t)b*NN + n0 + ty*4 + i];
        ri[i] = rinv[(size_t)b*NN + n0 + ty*4 + i];
        cm[i] = cmax[(size_t)b*NN + m0 + tx*4 + i];
        ci[i] = cinv[(size_t)b*NN + m0 + tx*4 + i];
    }

    #pragma unroll
    for (int i = 0; i < 4; i++) {
        int n = n0 + ty*4 + i;
        float4 v1, v2;
        float* pv1 = (float*)&v1;
        float* pv2 = (float*)&v2;
        #pragma unroll
        for (int j = 0; j < 4; j++) {
            pv1[j] = __expf(e[i][j] - rm[i]) * ri[i];
            pv2[j] = __expf(e[i][j] - cm[j]) * ci[j];
        }
        size_t base = (size_t)b*NN*NN + (size_t)n*NN + m0 + tx*4;
        *(float4*)(P1 + base) = v1;
        *(float4*)(P2 + base) = v2;
    }
}

// ======================================================================
// tf32 tensor-core GEMM (mma.sync.m16n8k8):
//   variant 0: outB[c][m] = sum_n V[c][n] * P1[m][n]   (B = P1^T)
//   variant 1: outC[c][m] = sum_n V[c][n] * P2[n][m]
// Block tile 128(M=C) x 128(N=m), BK=16. 8 warps as 2(M) x 4(N),
// warp tile 64x32 -> Mfrag=4, Nfrag=4. fp32->tf32 converted at smem store.
// ======================================================================
__device__ __forceinline__ float f2tf32(float x) {
    uint32_t r;
    asm("cvt.rna.tf32.f32 %0, %1;" : "=r"(r) : "f"(x));
    return __uint_as_float(r);
}

__global__ __launch_bounds__(256, 2) void gemm_vp_mma(
    const float* __restrict__ V,
    const float* __restrict__ P1f, const float* __restrict__ P2f,
    float* __restrict__ outBp, float* __restrict__ outCp)
{
    const int z = blockIdx.z;
    const int b = z >> 1;
    const int variant = z & 1;              // 0: trans(P1)->outB, 1: P2->outC
    const float* __restrict__ P = variant ? P2f : P1f;
    float* __restrict__ out     = variant ? outCp : outBp;

    const int c0 = blockIdx.y * 128;
    const int m0 = blockIdx.x * 128;

    const int tid  = threadIdx.x;
    const int lane = tid & 31;
    const int warp = tid >> 5;              // 0..7
    const int wm   = warp & 1;              // 2 warps in M
    const int wn   = warp >> 1;             // 4 warps in N

    __shared__ float As[16][132];
    __shared__ float Bs[16][132];

    const float* Vb = V + (size_t)b*NC*NN;
    const float* Pb = P + (size_t)b*NN*NN;

    float acc[4][4][4];
    #pragma unroll
    for (int i = 0; i < 4; i++)
        #pragma unroll
        for (int j = 0; j < 4; j++)
            #pragma unroll
            for (int r = 0; r < 4; r++) acc[i][j][r] = 0.f;

    const int arow = tid >> 1;              // 0..127
    const int akc  = (tid & 1) * 8;         // 0 or 8
    const int bk   = tid >> 4;              // 0..15
    const int bm   = (tid & 15) * 8;        // 0..120

    for (int k0 = 0; k0 < NN; k0 += 16) {
        // ---- load A tile: V[c0+r][k0 + kc..kc+7] -> As[k][r] ----
        {
            const float* src = Vb + (size_t)(c0 + arow)*NN + k0 + akc;
            float4 v0 = *(const float4*)(src);
            float4 v1 = *(const float4*)(src + 4);
            As[akc+0][arow] = f2tf32(v0.x); As[akc+1][arow] = f2tf32(v0.y);
            As[akc+2][arow] = f2tf32(v0.z); As[akc+3][arow] = f2tf32(v0.w);
            As[akc+4][arow] = f2tf32(v1.x); As[akc+5][arow] = f2tf32(v1.y);
            As[akc+6][arow] = f2tf32(v1.z); As[akc+7][arow] = f2tf32(v1.w);
        }
        // ---- load B tile ----
        if (variant) {
            // Bs[k][m] = P[k0+k][m0+m]
            const float* src = Pb + (size_t)(k0 + bk)*NN + m0 + bm;
            float4 v0 = *(const float4*)(src);
            float4 v1 = *(const float4*)(src + 4);
            Bs[bk][bm+0] = f2tf32(v0.x); Bs[bk][bm+1] = f2tf32(v0.y);
            Bs[bk][bm+2] = f2tf32(v0.z); Bs[bk][bm+3] = f2tf32(v0.w);
            Bs[bk][bm+4] = f2tf32(v1.x); Bs[bk][bm+5] = f2tf32(v1.y);
            Bs[bk][bm+6] = f2tf32(v1.z); Bs[bk][bm+7] = f2tf32(v1.w);
        } else {
            // Bs[k][m] = P[m0+m][k0+k]
            const float* src = Pb + (size_t)(m0 + arow)*NN + k0 + akc;
            float4 v0 = *(const float4*)(src);
            float4 v1 = *(const float4*)(src + 4);
            Bs[akc+0][arow] = f2tf32(v0.x); Bs[akc+1][arow] = f2tf32(v0.y);
            Bs[akc+2][arow] = f2tf32(v0.z); Bs[akc+3][arow] = f2tf32(v0.w);
            Bs[akc+4][arow] = f2tf32(v1.x); Bs[akc+5][arow] = f2tf32(v1.y);
            Bs[akc+6][arow] = f2tf32(v1.z); Bs[akc+7][arow] = f2tf32(v1.w);
        }
        __syncthreads();

        #pragma unroll
        for (int kk = 0; kk < 2; kk++) {
            const int kb = kk*8 + (lane & 3);
            float a[4][4];
            #pragma unroll
            for (int mf = 0; mf < 4; mf++) {
                int row = wm*64 + mf*16 + (lane >> 2);
                a[mf][0] = As[kb  ][row];
                a[mf][1] = As[kb  ][row+8];
                a[mf][2] = As[kb+4][row];
                a[mf][3] = As[kb+4][row+8];
            }
            float bf[4][2];
            #pragma unroll
            for (int nf = 0; nf < 4; nf++) {
                int col = wn*32 + nf*8 + (lane >> 2);
                bf[nf][0] = Bs[kb  ][col];
                bf[nf][1] = Bs[kb+4][col];
            }
            #pragma unroll
            for (int mf = 0; mf < 4; mf++)
                #pragma unroll
                for (int nf = 0; nf < 4; nf++) {
                    asm volatile(
                        "mma.sync.aligned.m16n8k8.row.col.f32.tf32.tf32.f32 "
                        "{%0,%1,%2,%3}, {%4,%5,%6,%7}, {%8,%9}, {%0,%1,%2,%3};"
                        : "+f"(acc[mf][nf][0]), "+f"(acc[mf][nf][1]),
                          "+f"(acc[mf][nf][2]), "+f"(acc[mf][nf][3])
                        : "r"(__float_as_uint(a[mf][0])), "r"(__float_as_uint(a[mf][1])),
                          "r"(__float_as_uint(a[mf][2])), "r"(__float_as_uint(a[mf][3])),
                          "r"(__float_as_uint(bf[nf][0])), "r"(__float_as_uint(bf[nf][1])));
                }
        }
        __syncthreads();
    }

    float* ob = out + (size_t)b*NC*NN;
    #pragma unroll
    for (int mf = 0; mf < 4; mf++) {
        int row = c0 + wm*64 + mf*16 + (lane >> 2);
        #pragma unroll
        for (int nf = 0; nf < 4; nf++) {
            int col = m0 + wn*32 + nf*8 + (lane & 3)*2;
            *(float2*)(ob + (size_t)row*NN + col) =
                make_float2(acc[mf][nf][0], acc[mf][nf][1]);
            *(float2*)(ob + (size_t)(row+8)*NN + col) =
                make_float2(acc[mf][nf][2], acc[mf][nf][3]);
        }
    }
}

// ======================================================================
// SE layer pieces
// ======================================================================
__global__ __launch_bounds__(256) void se_reduce_k(
    const float* __restrict__ comp, float* __restrict__ y0)
{
    int b = blockIdx.y, c = blockIdx.x;
    const float* p = comp + ((size_t)b*NC + c)*NPIX;
    float s = 0.f;
    for (int i = threadIdx.x; i < NPIX; i += 256) s += p[i];
    #pragma unroll
    for (int o = 16; o; o >>= 1) s += __shfl_xor_sync(0xffffffffu, s, o);
    __shared__ float red[8];
    if ((threadIdx.x & 31) == 0) red[threadIdx.x >> 5] = s;
    __syncthreads();
    if (threadIdx.x == 0) {
        float t = 0.f;
        for (int i = 0; i < 8; i++) t += red[i];
        y0[b*NC + c] = t * (1.f / NPIX);
    }
}

__global__ __launch_bounds__(256) void se_mlp_k(
    const float* __restrict__ y0, const float* __restrict__ w1,
    const float* __restrict__ w2, float* __restrict__ se)
{
    int b = blockIdx.x, tid = threadIdx.x;
    __shared__ float ys[NC];
    __shared__ float hs[32];
    ys[tid] = y0[b*NC + tid];
    __syncthreads();
    if (tid < 32) {
        float a = 0.f;
        for (int j = 0; j < NC; j++) a += ys[j] * w1[tid*NC + j];
        hs[tid] = fmaxf(a, 0.f);
    }
    __syncthreads();
    float a = 0.f;
    #pragma unroll
    for (int j = 0; j < 32; j++) a += hs[j] * w2[tid*32 + j];
    se[b*NC + tid] = 1.f / (1.f + __expf(-a));
}

__global__ __launch_bounds__(256) void se_scale_k(
    const float* __restrict__ comp, const float* __restrict__ se,
    float* __restrict__ outA)
{
    size_t i = (size_t)blockIdx.x * 256 + threadIdx.x;
    if (i < (size_t)NB*NC*NPIX) {
        size_t bc = i >> 12;                 // / NPIX
        outA[i] = comp[i] * se[bc];
    }
}

// ======================================================================
// host launcher
// ======================================================================
template <typename T>
static float* symaddr(T& sym) {
    void* p = nullptr;
    cudaGetSymbolAddress(&p, sym);
    return (float*)p;
}

extern "C" void kernel_launch(void* const* d_in, const int* in_sizes, int n_in,
                              void* d_out, int out_size)
{
    const float* x      = (const float*)d_in[0];
    const float* mmask  = (const float*)d_in[1];
    const float* amask  = (const float*)d_in[2];
    const float* w_mp   = (const float*)d_in[3];
    const float* b_mp   = (const float*)d_in[4];
    const float* w_ap   = (const float*)d_in[5];
    const float* b_ap   = (const float*)d_in[6];
    const float* w_q    = (const float*)d_in[7];
    const float* b_q    = (const float*)d_in[8];
    const float* w_k    = (const float*)d_in[9];
    const float* b_k    = (const float*)d_in[10];
    const float* w_v    = (const float*)d_in[11];
    const float* b_v    = (const float*)d_in[12];
    const float* w_comp = (const float*)d_in[13];
    const float* b_comp = (const float*)d_in[14];
    const float* w_out  = (const float*)d_in[15];
    const float* b_out  = (const float*)d_in[16];
    const float* w_se1  = (const float*)d_in[17];
    const float* w_se2  = (const float*)d_in[18];
    float* out = (float*)d_out;

    float* modal  = symaddr(g_modal);
    float* amodal = symaddr(g_amodal);
    float* q      = symaddr(g_q);
    float* k      = symaddr(g_kk);
    float* v      = symaddr(g_v);
    float* comp   = symaddr(g_comp);
    float* outA   = symaddr(g_outA);
    float* outB   = symaddr(g_outB);
    float* outC   = symaddr(g_outC);
    float* P1     = symaddr(g_P1);
    float* P2     = symaddr(g_P2);
    float* rmax   = symaddr(g_rmax);
    float* rinv   = symaddr(g_rinv);
    float* cmax   = symaddr(g_cmax);
    float* cinv   = symaddr(g_cinv);
    float* y0     = symaddr(g_y0);
    float* se     = symaddr(g_se);
    float* part   = symaddr(g_part);

    const int BSX = NC*NPIX;      // x batch stride
    const int BSM = NCLS*NPIX;    // mask / modal batch stride
    const int BSQ = QKD*NPIX;

    // ---- modal prediction conv (K-split x4, masked combine) ----
    conv3x3_k<<<dim3(4, 3*4, NB), 256>>>(x, NC, BSX, nullptr,0,0, nullptr,0,0,
        w_mp, b_mp, modal, BSM, NCLS, 3, nullptr, 0, 4, 64, part);
    conv_combine_k<<<(NB*NCLS*NPIX + 255)/256, 256>>>(part, 4, b_mp, modal, BSM, NCLS, mmask, BSM);

    // ---- amodal prediction conv ----
    conv3x3_k<<<dim3(4, 3*4, NB), 256>>>(x, NC, BSX, nullptr,0,0, nullptr,0,0,
        w_ap, b_ap, amodal, BSM, NCLS, 3, nullptr, 0, 4, 64, part);
    conv_combine_k<<<(NB*NCLS*NPIX + 255)/256, 256>>>(part, 4, b_ap, amodal, BSM, NCLS, amask, BSM);

    // ---- q conv (Cin=275, K-split x4) ----
    conv3x3_k<<<dim3(4, 4*4, NB), 256>>>(x, NC, BSX, mmask, NCLS, BSM, nullptr,0,0,
        w_q, b_q, q, BSQ, QKD, 4, nullptr, 0, 4, 69, part);
    conv_combine_k<<<(NB*QKD*NPIX + 255)/256, 256>>>(part, 4, b_q, q, BSQ, QKD, nullptr, 0);

    // ---- k conv ----
    conv3x3_k<<<dim3(4, 4*4, NB), 256>>>(x, NC, BSX, amask, NCLS, BSM, nullptr,0,0,
        w_k, b_k, k, BSQ, QKD, 4, nullptr, 0, 4, 69, part);
    conv_combine_k<<<(NB*QKD*NPIX + 255)/256, 256>>>(part, 4, b_k, k, BSQ, QKD, nullptr, 0);

    // ---- v conv (direct) ----
    conv3x3_k<<<dim3(4, 32, NB), 256>>>(x, NC, BSX, nullptr,0,0, nullptr,0,0,
        w_v, b_v, v, BSX, NC, 32, nullptr, 0, 1, NC, nullptr);

    // ---- comp conv over concat(x, modal_x, amodal_x) ----
    conv3x3_k<<<dim3(4, 32, NB), 256>>>(x, NC, BSX, modal, NCLS, BSM, amodal, NCLS, BSM,
        w_comp, b_comp, comp, BSX, NC, 32, nullptr, 0, 1, NC + 2*NCLS, nullptr);

    // ---- SE layer -> out_a ----
    se_reduce_k<<<dim3(NC, NB), 256>>>(comp, y0);
    se_mlp_k<<<NB, 256>>>(y0, w_se1, w_se2, se);
    se_scale_k<<<(NB*NC*NPIX)/256, 256>>>(comp, se, outA);

    // ---- attention stats: rows of E (q,k) and columns of E (k,q) ----
    attn_stats_k<<<dim3(NN/64, NB), 256>>>(q, k, rmax, rinv);
    attn_stats_k<<<dim3(NN/64, NB), 256>>>(k, q, cmax, cinv);

    // ---- normalized softmax matrices ----
    attn_p_k<<<dim3(NN/64, NN/64, NB), 256>>>(q, k, rmax, rinv, cmax, cinv, P1, P2);

    // ---- out_b = V * P1^T ; out_c = V * P2  (tf32 tensor cores, fused) ----
    gemm_vp_mma<<<dim3(NN/128, NC/128, NB*2), 256>>>(v, P1, P2, outB, outC);

    // ---- final conv over concat(out_a, out_b, out_c) ----
    conv3x3_k<<<dim3(4, 32, NB), 256>>>(outA, NC, BSX, outB, NC, BSX, outC, NC, BSX,
        w_out, b_out, out, BSX, NC, 32, nullptr, 0, 1, 3*NC, nullptr);
}

// round 7
// speedup vs baseline: 1.7873x; 1.0076x over previous
#include <cuda_runtime.h>
#include <cstdint>

// ---------------- problem constants ----------------
#define NB   2
#define NC   256
#define HH   64
#define NPIX 4096           // 64*64
#define NN   4096           // attention sequence length
#define QKD  32
#define NCLS 19

// ---------------- scratch (device globals; no allocation allowed) ----------
__device__ float g_modal [NB*NCLS*NPIX];
__device__ float g_amodal[NB*NCLS*NPIX];
__device__ float g_q     [NB*QKD*NPIX];
__device__ float g_kk    [NB*QKD*NPIX];
__device__ float g_v     [(size_t)NB*NC*NPIX];
__device__ float g_comp  [(size_t)NB*NC*NPIX];
__device__ float g_outA  [(size_t)NB*NC*NPIX];
__device__ float g_outB  [(size_t)NB*NC*NPIX];
__device__ float g_outC  [(size_t)NB*NC*NPIX];
__device__ float g_P1    [(size_t)NB*NN*NN];
__device__ float g_P2    [(size_t)NB*NN*NN];
__device__ float g_rmax  [NB*NN];
__device__ float g_rinv  [NB*NN];
__device__ float g_cmax  [NB*NN];
__device__ float g_cinv  [NB*NN];
__device__ float g_y0    [NB*NC];
__device__ float g_se    [NB*NC];

__device__ __forceinline__ float f2tf32(float x) {
    uint32_t r;
    asm("cvt.rna.tf32.f32 %0, %1;" : "=r"(r) : "f"(x));
    return __uint_as_float(r);
}

#define MMA_TF32(acc, av, bv)                                              \
    asm volatile(                                                          \
        "mma.sync.aligned.m16n8k8.row.col.f32.tf32.tf32.f32 "              \
        "{%0,%1,%2,%3}, {%4,%5,%6,%7}, {%8,%9}, {%0,%1,%2,%3};"            \
        : "+f"((acc)[0]), "+f"((acc)[1]), "+f"((acc)[2]), "+f"((acc)[3])   \
        : "r"(__float_as_uint((av)[0])), "r"(__float_as_uint((av)[1])),    \
          "r"(__float_as_uint((av)[2])), "r"(__float_as_uint((av)[3])),    \
          "r"(__float_as_uint((bv)[0])), "r"(__float_as_uint((bv)[1])))

// ======================================================================
// Implicit-GEMM 3x3 SAME conv, 3xTF32 (hi/lo split) => ~fp32 precision.
//   out[oc][pix] = bias[oc] + sum_k W[oc][k] * im2col[k][pix]
// Input = concat of up to 3 NCHW segments. Optional mask epilogue.
// Block tile 128(oc) x 128(pix), BK=16. 8 warps 2(M)x4(N), warp 64x32.
// ======================================================================
__global__ __launch_bounds__(256, 2) void conv_mma(
    const float* __restrict__ p0, int c0, int bs0,
    const float* __restrict__ p1, int c1, int bs1,
    const float* __restrict__ p2, int c2, int bs2,
    const float* __restrict__ wt,    // [Cout][Cin*9]
    const float* __restrict__ bias,  // [Cout]
    float* __restrict__ out, int outBS, int Cout,
    const float* __restrict__ mask, int maskBS)
{
    const int Cin  = c0 + c1 + c2;
    const int Ktot = Cin * 9;
    const int b    = blockIdx.z;
    const int ocg  = blockIdx.y * 128;
    const int m0   = blockIdx.x * 128;

    const int tid  = threadIdx.x;
    const int lane = tid & 31;
    const int warp = tid >> 5;
    const int wm   = warp & 1;
    const int wn   = warp >> 1;

    __shared__ float Ah[16][132];
    __shared__ float Al[16][132];
    __shared__ float Bh[16][132];
    __shared__ float Bl[16][132];

    float acc[4][4][4];
    #pragma unroll
    for (int i = 0; i < 4; i++)
        #pragma unroll
        for (int j = 0; j < 4; j++)
            #pragma unroll
            for (int r = 0; r < 4; r++) acc[i][j][r] = 0.f;

    const int arow = tid >> 1;              // 0..127 (oc within tile)
    const int akc  = (tid & 1) * 8;         // 0 or 8
    const int bk   = tid >> 4;              // 0..15  (k within tile)
    const int bm   = (tid & 15) * 8;        // 0..120 (pixel within tile)

    const int mpix = m0 + bm;
    const int py   = mpix >> 6;
    const int px   = mpix & 63;

    for (int k0 = 0; k0 < Ktot; k0 += 16) {
        // ---- A tile: weights (hi/lo split) ----
        {
            const int oc = ocg + arow;
            const float* wrow = wt + (size_t)oc*Ktot + k0 + akc;
            #pragma unroll
            for (int j = 0; j < 8; j++) {
                int kk = k0 + akc + j;
                float v = (oc < Cout && kk < Ktot) ? wrow[j] : 0.f;
                float hi = f2tf32(v);
                Ah[akc+j][arow] = hi;
                Al[akc+j][arow] = f2tf32(v - hi);
            }
        }
        // ---- B tile: im2col gather (hi/lo split) ----
        {
            const int kB = k0 + bk;
            float vb[8];
            #pragma unroll
            for (int j = 0; j < 8; j++) vb[j] = 0.f;
            if (kB < Ktot) {
                int ic = kB / 9;
                int t  = kB - ic*9;
                int dy = t/3 - 1;
                int dx = t - (t/3)*3 - 1;
                const float* src;
                if (ic < c0)           src = p0 + (size_t)b*bs0 + (size_t)ic        *NPIX;
                else if (ic < c0+c1)   src = p1 + (size_t)b*bs1 + (size_t)(ic-c0)   *NPIX;
                else                   src = p2 + (size_t)b*bs2 + (size_t)(ic-c0-c1)*NPIX;
                int yy = py + dy;
                if (yy >= 0 && yy < HH) {
                    const float* r = src + yy*HH + px + dx;
                    #pragma unroll
                    for (int j = 0; j < 8; j++) {
                        int xx = px + dx + j;
                        if (xx >= 0 && xx < HH) vb[j] = r[j];
                    }
                }
            }
            #pragma unroll
            for (int j = 0; j < 8; j++) {
                float hi = f2tf32(vb[j]);
                Bh[bk][bm+j] = hi;
                Bl[bk][bm+j] = f2tf32(vb[j] - hi);
            }
        }
        __syncthreads();

        #pragma unroll
        for (int kk = 0; kk < 2; kk++) {
            const int kb = kk*8 + (lane & 3);
            float ah[4][4], al[4][4];
            #pragma unroll
            for (int mf = 0; mf < 4; mf++) {
                int row = wm*64 + mf*16 + (lane >> 2);
                ah[mf][0] = Ah[kb  ][row];   al[mf][0] = Al[kb  ][row];
                ah[mf][1] = Ah[kb  ][row+8]; al[mf][1] = Al[kb  ][row+8];
                ah[mf][2] = Ah[kb+4][row];   al[mf][2] = Al[kb+4][row];
                ah[mf][3] = Ah[kb+4][row+8]; al[mf][3] = Al[kb+4][row+8];
            }
            float bh[4][2], bl[4][2];
            #pragma unroll
            for (int nf = 0; nf < 4; nf++) {
                int col = wn*32 + nf*8 + (lane >> 2);
                bh[nf][0] = Bh[kb  ][col];   bl[nf][0] = Bl[kb  ][col];
                bh[nf][1] = Bh[kb+4][col];   bl[nf][1] = Bl[kb+4][col];
            }
            #pragma unroll
            for (int mf = 0; mf < 4; mf++)
                #pragma unroll
                for (int nf = 0; nf < 4; nf++) {
                    MMA_TF32(acc[mf][nf], al[mf], bh[nf]);  // lo*hi
                    MMA_TF32(acc[mf][nf], ah[mf], bl[nf]);  // hi*lo
                    MMA_TF32(acc[mf][nf], ah[mf], bh[nf]);  // hi*hi (last: largest term)
                }
        }
        __syncthreads();
    }

    // ---- epilogue: bias (+ optional mask), write NCHW ----
    float* ob = out + (size_t)b*outBS;
    const float* mb = mask ? (mask + (size_t)b*maskBS) : nullptr;
    #pragma unroll
    for (int mf = 0; mf < 4; mf++) {
        int r0 = ocg + wm*64 + mf*16 + (lane >> 2);
        int r1 = r0 + 8;
        #pragma unroll
        for (int nf = 0; nf < 4; nf++) {
            int col = m0 + wn*32 + nf*8 + (lane & 3)*2;
            if (r0 < Cout) {
                float v0 = acc[mf][nf][0] + bias[r0];
                float v1 = acc[mf][nf][1] + bias[r0];
                if (mb) {
                    v0 *= mb[(size_t)r0*NPIX + col];
                    v1 *= mb[(size_t)r0*NPIX + col + 1];
                }
                *(float2*)(ob + (size_t)r0*NPIX + col) = make_float2(v0, v1);
            }
            if (r1 < Cout) {
                float v0 = acc[mf][nf][2] + bias[r1];
                float v1 = acc[mf][nf][3] + bias[r1];
                if (mb) {
                    v0 *= mb[(size_t)r1*NPIX + col];
                    v1 *= mb[(size_t)r1*NPIX + col + 1];
                }
                *(float2*)(ob + (size_t)r1*NPIX + col) = make_float2(v0, v1);
            }
        }
    }
}

// ======================================================================
// Flash-style softmax stats over rows of E = Q^T K
// ======================================================================
__global__ __launch_bounds__(256) void attn_stats_k(
    const float* __restrict__ Q, const float* __restrict__ K,
    float* __restrict__ omax, float* __restrict__ oinv)
{
    const int b  = blockIdx.y;
    const int n0 = blockIdx.x * 64;
    const int tid = threadIdx.x;
    const int tx = tid & 15, ty = tid >> 4;

    __shared__ float qs[32][64];
    __shared__ float ks[32][64];
    __shared__ float redM[64][17];
    __shared__ float redS[64][17];

    const float* qb = Q + (size_t)b*QKD*NN;
    const float* kb = K + (size_t)b*QKD*NN;

    for (int i = tid; i < 32*16; i += 256) {
        int d = i >> 4, c4 = i & 15;
        *(float4*)&qs[d][c4*4] = *(const float4*)(qb + (size_t)d*NN + n0 + c4*4);
    }

    float M[4], S[4];
    #pragma unroll
    for (int i = 0; i < 4; i++) { M[i] = -1e30f; S[i] = 0.f; }

    for (int m0 = 0; m0 < NN; m0 += 64) {
        __syncthreads();
        for (int i = tid; i < 32*16; i += 256) {
            int d = i >> 4, c4 = i & 15;
            *(float4*)&ks[d][c4*4] = *(const float4*)(kb + (size_t)d*NN + m0 + c4*4);
        }
        __syncthreads();

        float e[4][4];
        #pragma unroll
        for (int i = 0; i < 4; i++)
            #pragma unroll
            for (int j = 0; j < 4; j++) e[i][j] = 0.f;

        #pragma unroll
        for (int d = 0; d < 32; d++) {
            float4 a  = *(const float4*)&qs[d][ty*4];
            float4 bv = *(const float4*)&ks[d][tx*4];
            float aa[4] = {a.x, a.y, a.z, a.w};
            float bb[4] = {bv.x, bv.y, bv.z, bv.w};
            #pragma unroll
            for (int i = 0; i < 4; i++)
                #pragma unroll
                for (int j = 0; j < 4; j++) e[i][j] += aa[i]*bb[j];
        }
        #pragma unroll
        for (int i = 0; i < 4; i++) {
            float lm = fmaxf(fmaxf(e[i][0], e[i][1]), fmaxf(e[i][2], e[i][3]));
            float nm = fmaxf(M[i], lm);
            float s = S[i] * __expf(M[i] - nm);
            #pragma unroll
            for (int j = 0; j < 4; j++) s += __expf(e[i][j] - nm);
            M[i] = nm; S[i] = s;
        }
    }
    __syncthreads();
    #pragma unroll
    for (int i = 0; i < 4; i++) { redM[ty*4+i][tx] = M[i]; redS[ty*4+i][tx] = S[i]; }
    __syncthreads();
    if (tid < 64) {
        float m = redM[tid][0], s = redS[tid][0];
        for (int j = 1; j < 16; j++) {
            float m2 = redM[tid][j], s2 = redS[tid][j];
            float nm = fmaxf(m, m2);
            s = s*__expf(m - nm) + s2*__expf(m2 - nm);
            m = nm;
        }
        omax[(size_t)b*NN + n0 + tid] = m;
        oinv[(size_t)b*NN + n0 + tid] = 1.f / s;
    }
}

// ======================================================================
// P kernel: compute E tile once, write both normalized softmax matrices.
// ======================================================================
__global__ __launch_bounds__(256) void attn_p_k(
    const float* __restrict__ Q, const float* __restrict__ K,
    const float* __restrict__ rmax, const float* __restrict__ rinv,
    const float* __restrict__ cmax, const float* __restrict__ cinv,
    float* __restrict__ P1, float* __restrict__ P2)
{
    const int b  = blockIdx.z;
    const int n0 = blockIdx.y * 64;
    const int m0 = blockIdx.x * 64;
    const int tid = threadIdx.x;
    const int tx = tid & 15, ty = tid >> 4;

    __shared__ float qs[32][64];
    __shared__ float ks[32][64];

    const float* qb = Q + (size_t)b*QKD*NN;
    const float* kb = K + (size_t)b*QKD*NN;

    for (int i = tid; i < 32*16; i += 256) {
        int d = i >> 4, c4 = i & 15;
        *(float4*)&qs[d][c4*4] = *(const float4*)(qb + (size_t)d*NN + n0 + c4*4);
        *(float4*)&ks[d][c4*4] = *(const float4*)(kb + (size_t)d*NN + m0 + c4*4);
    }
    __syncthreads();

    float e[4][4];
    #pragma unroll
    for (int i = 0; i < 4; i++)
        #pragma unroll
        for (int j = 0; j < 4; j++) e[i][j] = 0.f;

    #pragma unroll
    for (int d = 0; d < 32; d++) {
        float4 a  = *(const float4*)&qs[d][ty*4];
        float4 bv = *(const float4*)&ks[d][tx*4];
        float aa[4] = {a.x, a.y, a.z, a.w};
        float bb[4] = {bv.x, bv.y, bv.z, bv.w};
        #pragma unroll
        for (int i = 0; i < 4; i++)
            #pragma unroll
            for (int j = 0; j < 4; j++) e[i][j] += aa[i]*bb[j];
    }

    float rm[4], ri[4], cm[4], ci[4];
    #pragma unroll
    for (int i = 0; i < 4; i++) {
        rm[i] = rmax[(size_t)b*NN + n0 + ty*4 + i];
        ri[i] = rinv[(size_t)b*NN + n0 + ty*4 + i];
        cm[i] = cmax[(size_t)b*NN + m0 + tx*4 + i];
        ci[i] = cinv[(size_t)b*NN + m0 + tx*4 + i];
    }

    #pragma unroll
    for (int i = 0; i < 4; i++) {
        int n = n0 + ty*4 + i;
        float4 v1, v2;
        float* pv1 = (float*)&v1;
        float* pv2 = (float*)&v2;
        #pragma unroll
        for (int j = 0; j < 4; j++) {
            pv1[j] = __expf(e[i][j] - rm[i]) * ri[i];
            pv2[j] = __expf(e[i][j] - cm[j]) * ci[j];
        }
        size_t base = (size_t)b*NN*NN + (size_t)n*NN + m0 + tx*4;
        *(float4*)(P1 + base) = v1;
        *(float4*)(P2 + base) = v2;
    }
}

// ======================================================================
// tf32 tensor-core GEMM for out_b / out_c (single-pass tf32; validated)
// ======================================================================
__global__ __launch_bounds__(256, 2) void gemm_vp_mma(
    const float* __restrict__ V,
    const float* __restrict__ P1f, const float* __restrict__ P2f,
    float* __restrict__ outBp, float* __restrict__ outCp)
{
    const int z = blockIdx.z;
    const int b = z >> 1;
    const int variant = z & 1;              // 0: trans(P1)->outB, 1: P2->outC
    const float* __restrict__ P = variant ? P2f : P1f;
    float* __restrict__ out     = variant ? outCp : outBp;

    const int c0 = blockIdx.y * 128;
    const int m0 = blockIdx.x * 128;

    const int tid  = threadIdx.x;
    const int lane = tid & 31;
    const int warp = tid >> 5;
    const int wm   = warp & 1;
    const int wn   = warp >> 1;

    __shared__ float As[16][132];
    __shared__ float Bs[16][132];

    const float* Vb = V + (size_t)b*NC*NN;
    const float* Pb = P + (size_t)b*NN*NN;

    float acc[4][4][4];
    #pragma unroll
    for (int i = 0; i < 4; i++)
        #pragma unroll
        for (int j = 0; j < 4; j++)
            #pragma unroll
            for (int r = 0; r < 4; r++) acc[i][j][r] = 0.f;

    const int arow = tid >> 1;
    const int akc  = (tid & 1) * 8;
    const int bk   = tid >> 4;
    const int bm   = (tid & 15) * 8;

    for (int k0 = 0; k0 < NN; k0 += 16) {
        {
            const float* src = Vb + (size_t)(c0 + arow)*NN + k0 + akc;
            float4 v0 = *(const float4*)(src);
            float4 v1 = *(const float4*)(src + 4);
            As[akc+0][arow] = f2tf32(v0.x); As[akc+1][arow] = f2tf32(v0.y);
            As[akc+2][arow] = f2tf32(v0.z); As[akc+3][arow] = f2tf32(v0.w);
            As[akc+4][arow] = f2tf32(v1.x); As[akc+5][arow] = f2tf32(v1.y);
            As[akc+6][arow] = f2tf32(v1.z); As[akc+7][arow] = f2tf32(v1.w);
        }
        if (variant) {
            const float* src = Pb + (size_t)(k0 + bk)*NN + m0 + bm;
            float4 v0 = *(const float4*)(src);
            float4 v1 = *(const float4*)(src + 4);
            Bs[bk][bm+0] = f2tf32(v0.x); Bs[bk][bm+1] = f2tf32(v0.y);
            Bs[bk][bm+2] = f2tf32(v0.z); Bs[bk][bm+3] = f2tf32(v0.w);
            Bs[bk][bm+4] = f2tf32(v1.x); Bs[bk][bm+5] = f2tf32(v1.y);
            Bs[bk][bm+6] = f2tf32(v1.z); Bs[bk][bm+7] = f2tf32(v1.w);
        } else {
            const float* src = Pb + (size_t)(m0 + arow)*NN + k0 + akc;
            float4 v0 = *(const float4*)(src);
            float4 v1 = *(const float4*)(src + 4);
            Bs[akc+0][arow] = f2tf32(v0.x); Bs[akc+1][arow] = f2tf32(v0.y);
            Bs[akc+2][arow] = f2tf32(v0.z); Bs[akc+3][arow] = f2tf32(v0.w);
            Bs[akc+4][arow] = f2tf32(v1.x); Bs[akc+5][arow] = f2tf32(v1.y);
            Bs[akc+6][arow] = f2tf32(v1.z); Bs[akc+7][arow] = f2tf32(v1.w);
        }
        __syncthreads();

        #pragma unroll
        for (int kk = 0; kk < 2; kk++) {
            const int kb = kk*8 + (lane & 3);
            float a[4][4];
            #pragma unroll
            for (int mf = 0; mf < 4; mf++) {
                int row = wm*64 + mf*16 + (lane >> 2);
                a[mf][0] = As[kb  ][row];
                a[mf][1] = As[kb  ][row+8];
                a[mf][2] = As[kb+4][row];
                a[mf][3] = As[kb+4][row+8];
            }
            float bf[4][2];
            #pragma unroll
            for (int nf = 0; nf < 4; nf++) {
                int col = wn*32 + nf*8 + (lane >> 2);
                bf[nf][0] = Bs[kb  ][col];
                bf[nf][1] = Bs[kb+4][col];
            }
            #pragma unroll
            for (int mf = 0; mf < 4; mf++)
                #pragma unroll
                for (int nf = 0; nf < 4; nf++)
                    MMA_TF32(acc[mf][nf], a[mf], bf[nf]);
        }
        __syncthreads();
    }

    float* ob = out + (size_t)b*NC*NN;
    #pragma unroll
    for (int mf = 0; mf < 4; mf++) {
        int row = c0 + wm*64 + mf*16 + (lane >> 2);
        #pragma unroll
        for (int nf = 0; nf < 4; nf++) {
            int col = m0 + wn*32 + nf*8 + (lane & 3)*2;
            *(float2*)(ob + (size_t)row*NN + col) =
                make_float2(acc[mf][nf][0], acc[mf][nf][1]);
            *(float2*)(ob + (size_t)(row+8)*NN + col) =
                make_float2(acc[mf][nf][2], acc[mf][nf][3]);
        }
    }
}

// ======================================================================
// SE layer pieces
// ======================================================================
__global__ __launch_bounds__(256) void se_reduce_k(
    const float* __restrict__ comp, float* __restrict__ y0)
{
    int b = blockIdx.y, c = blockIdx.x;
    const float* p = comp + ((size_t)b*NC + c)*NPIX;
    float s = 0.f;
    for (int i = threadIdx.x; i < NPIX; i += 256) s += p[i];
    #pragma unroll
    for (int o = 16; o; o >>= 1) s += __shfl_xor_sync(0xffffffffu, s, o);
    __shared__ float red[8];
    if ((threadIdx.x & 31) == 0) red[threadIdx.x >> 5] = s;
    __syncthreads();
    if (threadIdx.x == 0) {
        float t = 0.f;
        for (int i = 0; i < 8; i++) t += red[i];
        y0[b*NC + c] = t * (1.f / NPIX);
    }
}

__global__ __launch_bounds__(256) void se_mlp_k(
    const float* __restrict__ y0, const float* __restrict__ w1,
    const float* __restrict__ w2, float* __restrict__ se)
{
    int b = blockIdx.x, tid = threadIdx.x;
    __shared__ float ys[NC];
    __shared__ float hs[32];
    ys[tid] = y0[b*NC + tid];
    __syncthreads();
    if (tid < 32) {
        float a = 0.f;
        for (int j = 0; j < NC; j++) a += ys[j] * w1[tid*NC + j];
        hs[tid] = fmaxf(a, 0.f);
    }
    __syncthreads();
    float a = 0.f;
    #pragma unroll
    for (int j = 0; j < 32; j++) a += hs[j] * w2[tid*32 + j];
    se[b*NC + tid] = 1.f / (1.f + __expf(-a));
}

__global__ __launch_bounds__(256) void se_scale_k(
    const float* __restrict__ comp, const float* __restrict__ se,
    float* __restrict__ outA)
{
    size_t i = (size_t)blockIdx.x * 256 + threadIdx.x;
    if (i < (size_t)NB*NC*NPIX) {
        size_t bc = i >> 12;                 // / NPIX
        outA[i] = comp[i] * se[bc];
    }
}

// ======================================================================
// host launcher
// ======================================================================
template <typename T>
static float* symaddr(T& sym) {
    void* p = nullptr;
    cudaGetSymbolAddress(&p, sym);
    return (float*)p;
}

extern "C" void kernel_launch(void* const* d_in, const int* in_sizes, int n_in,
                              void* d_out, int out_size)
{
    const float* x      = (const float*)d_in[0];
    const float* mmask  = (const float*)d_in[1];
    const float* amask  = (const float*)d_in[2];
    const float* w_mp   = (const float*)d_in[3];
    const float* b_mp   = (const float*)d_in[4];
    const float* w_ap   = (const float*)d_in[5];
    const float* b_ap   = (const float*)d_in[6];
    const float* w_q    = (const float*)d_in[7];
    const float* b_q    = (const float*)d_in[8];
    const float* w_k    = (const float*)d_in[9];
    const float* b_k    = (const float*)d_in[10];
    const float* w_v    = (const float*)d_in[11];
    const float* b_v    = (const float*)d_in[12];
    const float* w_comp = (const float*)d_in[13];
    const float* b_comp = (const float*)d_in[14];
    const float* w_out  = (const float*)d_in[15];
    const float* b_out  = (const float*)d_in[16];
    const float* w_se1  = (const float*)d_in[17];
    const float* w_se2  = (const float*)d_in[18];
    float* out = (float*)d_out;

    float* modal  = symaddr(g_modal);
    float* amodal = symaddr(g_amodal);
    float* q      = symaddr(g_q);
    float* k      = symaddr(g_kk);
    float* v      = symaddr(g_v);
    float* comp   = symaddr(g_comp);
    float* outA   = symaddr(g_outA);
    float* outB   = symaddr(g_outB);
    float* outC   = symaddr(g_outC);
    float* P1     = symaddr(g_P1);
    float* P2     = symaddr(g_P2);
    float* rmax   = symaddr(g_rmax);
    float* rinv   = symaddr(g_rinv);
    float* cmax   = symaddr(g_cmax);
    float* cinv   = symaddr(g_cinv);
    float* y0     = symaddr(g_y0);
    float* se     = symaddr(g_se);

    const int BSX = NC*NPIX;      // x batch stride
    const int BSM = NCLS*NPIX;    // mask / modal batch stride
    const int BSQ = QKD*NPIX;

    const dim3 gSmall(NPIX/128, 1, NB);   // Cout <= 128
    const dim3 gBig  (NPIX/128, 2, NB);   // Cout = 256

    // ---- modal / amodal prediction convs (masked epilogue) ----
    conv_mma<<<gSmall, 256>>>(x, NC, BSX, nullptr,0,0, nullptr,0,0,
        w_mp, b_mp, modal, BSM, NCLS, mmask, BSM);
    conv_mma<<<gSmall, 256>>>(x, NC, BSX, nullptr,0,0, nullptr,0,0,
        w_ap, b_ap, amodal, BSM, NCLS, amask, BSM);

    // ---- q / k convs (concat(x, mask), Cin=275) ----
    conv_mma<<<gSmall, 256>>>(x, NC, BSX, mmask, NCLS, BSM, nullptr,0,0,
        w_q, b_q, q, BSQ, QKD, nullptr, 0);
    conv_mma<<<gSmall, 256>>>(x, NC, BSX, amask, NCLS, BSM, nullptr,0,0,
        w_k, b_k, k, BSQ, QKD, nullptr, 0);

    // ---- v conv ----
    conv_mma<<<gBig, 256>>>(x, NC, BSX, nullptr,0,0, nullptr,0,0,
        w_v, b_v, v, BSX, NC, nullptr, 0);

    // ---- comp conv over concat(x, modal_x, amodal_x) ----
    conv_mma<<<gBig, 256>>>(x, NC, BSX, modal, NCLS, BSM, amodal, NCLS, BSM,
        w_comp, b_comp, comp, BSX, NC, nullptr, 0);

    // ---- SE layer -> out_a ----
    se_reduce_k<<<dim3(NC, NB), 256>>>(comp, y0);
    se_mlp_k<<<NB, 256>>>(y0, w_se1, w_se2, se);
    se_scale_k<<<(NB*NC*NPIX)/256, 256>>>(comp, se, outA);

    // ---- attention stats: rows of E (q,k) and columns of E (k,q) ----
    attn_stats_k<<<dim3(NN/64, NB), 256>>>(q, k, rmax, rinv);
    attn_stats_k<<<dim3(NN/64, NB), 256>>>(k, q, cmax, cinv);

    // ---- normalized softmax matrices ----
    attn_p_k<<<dim3(NN/64, NN/64, NB), 256>>>(q, k, rmax, rinv, cmax, cinv, P1, P2);

    // ---- out_b = V * P1^T ; out_c = V * P2  (tf32 tensor cores, fused) ----
    gemm_vp_mma<<<dim3(NN/128, NC/128, NB*2), 256>>>(v, P1, P2, outB, outC);

    // ---- final conv over concat(out_a, out_b, out_c) ----
    conv_mma<<<gBig, 256>>>(outA, NC, BSX, outB, NC, BSX, outC, NC, BSX,
        w_out, b_out, out, BSX, NC, nullptr, 0);
}